// round 13
// baseline (speedup 1.0000x reference)
#include <cuda_runtime.h>
#include <cstdint>

// Problem constants
#define N_ 2
#define C_ 64
#define M_ 4800
#define K_ 64
#define EPS_ 1e-5f

// H B-fragment row stride in uint2 units (R10 layout, best measured)
#define HSTR 132

// ---------------- device scratch (no allocation allowed) ----------------
__device__ __align__(16) float g_B0t[N_ * M_ * C_];  // s0[c]*(W0q@query), [n][m][c]
__device__ __align__(16) float g_A0p[N_ * C_ * K_];  // s0*(W0s@scene)+t0  [n][j][k]
__device__ __align__(16) float g_Ts [N_ * C_ * K_];  // Wskip_xyz @ sx     [n][c][k]
__device__ __align__(16) float g_T1a[N_ * C_ * K_];  // s1a*(W1a_xyz@sx)+t1a [n][c][k]
// tf32 weight bit-patterns (row-major)
__device__ __align__(16) unsigned g_W1u[128 * 64];   // [Wskip ; s1a*W1a]
__device__ __align__(16) unsigned g_W2u[64 * 64];    // s1b*W1b
__device__ float g_t1b[C_];
__device__ float g_s0[C_], g_t0[C_], g_s1a[C_], g_t1a[C_];

// ---------------- helpers ----------------
__device__ __forceinline__ unsigned f2tf(float x) {
    unsigned u;
    asm("cvt.rna.tf32.f32 %0, %1;" : "=r"(u) : "f"(x));
    return u;
}

__device__ __forceinline__ void mma_tf32(float d[4], const unsigned a[4],
                                         unsigned b0, unsigned b1) {
    asm volatile(
        "mma.sync.aligned.m16n8k8.row.col.f32.tf32.tf32.f32 "
        "{%0,%1,%2,%3}, {%4,%5,%6,%7}, {%8,%9}, {%0,%1,%2,%3};"
        : "+f"(d[0]), "+f"(d[1]), "+f"(d[2]), "+f"(d[3])
        : "r"(a[0]), "r"(a[1]), "r"(a[2]), "r"(a[3]), "r"(b0), "r"(b1));
}

// ---------------- prep 1: BN folds + tf32 weights ----------------
__global__ void prep_weights(
    const float* __restrict__ W1a, const float* __restrict__ W1b,
    const float* __restrict__ Wskip,
    const float* __restrict__ g0, const float* __restrict__ b0,
    const float* __restrict__ m0, const float* __restrict__ v0,
    const float* __restrict__ g1a, const float* __restrict__ b1a,
    const float* __restrict__ m1a, const float* __restrict__ v1a,
    const float* __restrict__ g1b, const float* __restrict__ b1b,
    const float* __restrict__ m1b, const float* __restrict__ v1b)
{
    __shared__ float s1a_s[C_], s1b_s[C_];
    int t = threadIdx.x;
    if (t < C_) {
        float s = g0[t] * rsqrtf(v0[t] + EPS_);
        g_s0[t] = s; g_t0[t] = b0[t] - m0[t] * s;
        float sa = g1a[t] * rsqrtf(v1a[t] + EPS_);
        s1a_s[t] = sa; g_s1a[t] = sa; g_t1a[t] = b1a[t] - m1a[t] * sa;
        float sb = g1b[t] * rsqrtf(v1b[t] + EPS_);
        s1b_s[t] = sb;
        g_t1b[t] = b1b[t] - m1b[t] * sb;
    }
    __syncthreads();
    for (int i = t; i < 128 * 64; i += blockDim.x) {
        int r = i >> 6, j = i & 63;
        float v1 = (r < 64) ? Wskip[r * 67 + j]
                            : s1a_s[r - 64] * W1a[(r - 64) * 67 + j];
        g_W1u[i] = f2tf(v1);
        if (r < 64)
            g_W2u[i] = f2tf(s1b_s[r] * W1b[r * 64 + j]);
    }
}

// ---------------- prep 2: per-(n,k) tensors (A0', Ts, T1a') ----------------
__global__ void prep_nk(
    const float* __restrict__ scene_rgb,   // (N,C,1,K)
    const float* __restrict__ scene_xyz,   // (N,3,1,K)
    const float* __restrict__ mask,        // (N,1,1,K)
    const float* __restrict__ W0,          // (C,2C)
    const float* __restrict__ W1a,         // (C,C+3)
    const float* __restrict__ Wskip)       // (C,C+3)
{
    int gid = blockIdx.x * blockDim.x + threadIdx.x;   // 0 .. N*C*K-1 = 8191
    int n = gid >> 12;
    int r = gid & 4095;
    int c = r >> 6;
    int k = r & 63;
    const float* sc = scene_rgb + n * C_ * K_;
    float acc = 0.f;
#pragma unroll 8
    for (int j = 0; j < C_; ++j)
        acc = fmaf(W0[c * 2 * C_ + j], sc[j * K_ + k], acc);
    g_A0p[gid] = g_s0[c] * acc + g_t0[c];

    float mk = mask[n * K_ + k];
    float x0 = scene_xyz[n * 3 * K_ + 0 * K_ + k] * mk;
    float x1 = scene_xyz[n * 3 * K_ + 1 * K_ + k] * mk;
    float x2 = scene_xyz[n * 3 * K_ + 2 * K_ + k] * mk;
    g_Ts[gid]  = Wskip[c * 67 + 64] * x0 + Wskip[c * 67 + 65] * x1 +
                 Wskip[c * 67 + 66] * x2;
    g_T1a[gid] = g_s1a[c] * (W1a[c * 67 + 64] * x0 + W1a[c * 67 + 65] * x1 +
                             W1a[c * 67 + 66] * x2) + g_t1a[c];
}

// ---------------- prep 3: B0t[n][m][c] (transposed, smem-tiled) ----------------
__global__ void __launch_bounds__(128) prep_B0t(
    const float* __restrict__ query,   // (N,C,M,1)
    const float* __restrict__ W0)      // (C,2C)
{
    __shared__ float sq[64 * 32];
    __shared__ float sw[64 * 64];
    const int tid = threadIdx.x;
    const int bid = blockIdx.x;
    const int n = bid / 150;
    const int m0 = (bid % 150) * 32;

    for (int i = tid; i < 4096; i += 128) {
        int c = i >> 6, j = i & 63;
        sw[j * 64 + c] = W0[c * 2 * C_ + C_ + j];
    }
    const float* qn = query + n * C_ * M_;
    for (int i = tid; i < 2048; i += 128) {
        int j = i >> 5, ml = i & 31;
        sq[i] = qn[j * M_ + m0 + ml];
    }
    __syncthreads();

    const int ml = tid & 31;
    const int cg = tid >> 5;
    float acc[16];
#pragma unroll
    for (int i = 0; i < 16; ++i) acc[i] = 0.f;
#pragma unroll 4
    for (int j = 0; j < 64; ++j) {
        float qv = sq[j * 32 + ml];
        const float4* wr = reinterpret_cast<const float4*>(sw + j * 64 + cg * 16);
        float4 w0 = wr[0], w1 = wr[1], w2 = wr[2], w3 = wr[3];
        float wv[16] = {w0.x, w0.y, w0.z, w0.w, w1.x, w1.y, w1.z, w1.w,
                        w2.x, w2.y, w2.z, w2.w, w3.x, w3.y, w3.z, w3.w};
#pragma unroll
        for (int ci = 0; ci < 16; ++ci)
            acc[ci] = fmaf(wv[ci], qv, acc[ci]);
    }
    float* outp = g_B0t + n * M_ * C_ + (m0 + ml) * C_ + cg * 16;
#pragma unroll
    for (int ci = 0; ci < 16; ++ci)
        outp[ci] = acc[ci] * g_s0[cg * 16 + ci];
}

// ---------------- fused main kernel (mma.sync tf32) ----------------
// 512 threads, CTA = one m-tile (Tm=2; n-cols = mi*64 + k, 128 total).
// R10 smem layouts, NEW warp mapping: each warp owns TWO 16-row blocks and
// reuses every B-fragment load for both -> B-traffic halved vs R10.
// GEMM1: warp = (pair p=w&3 -> rbs 2p,2p+1 ; col-quarter q=w>>2, 4 nt).
// GEMM2: warp = (pair p2=w&1 ; col-eighth e8=w>>1, 2 nt).
// smem floats: sHs 8448 | sHs2 8448 | sSkip 8704 | sPM 512 | sF 128
#define SHS_F  0
#define SHS2_F 8448
#define SSK_F  16896
#define SPM_F  25600
#define SF_F   26112
#define SMEM_FLOATS 26240

extern "C" __global__ void __launch_bounds__(512) fused_main(
    const float* __restrict__ pre_xyz,   // (N,3,M)
    const float* __restrict__ Wout,      // (3,C+3)
    float* __restrict__ out)             // (N,3,M)
{
    extern __shared__ float smem[];
    unsigned* sHs   = reinterpret_cast<unsigned*>(smem + SHS_F);
    unsigned* sHs2  = reinterpret_cast<unsigned*>(smem + SHS2_F);
    float*    sSkip = smem + SSK_F;
    float*    sPM   = smem + SPM_F;   // [c][8] col-eighth maxima
    float*    sF    = smem + SF_F;

    const int tid  = threadIdx.x;
    const int lane = tid & 31;
    const int w    = tid >> 5;          // 0..15
    const int g    = lane >> 2;         // fragment group 0..7
    const int tq   = lane & 3;          // fragment quad-thread 0..3

    const int t   = blockIdx.x;         // 0..4799
    const int n_  = t / (M_ / 2);
    const int m0  = (t % (M_ / 2)) * 2;

    const float* A0n = g_A0p + n_ * 4096;
    const float* B0n = g_B0t + n_ * M_ * C_;
    const float* TsN = g_Ts  + n_ * 4096;
    const float* TaN = g_T1a + n_ * 4096;

    // ---- GEMM1 A-fragments: TWO row-blocks per warp ----
    const int p = w & 3;                // pair -> row-blocks 2p, 2p+1
    const int q = w >> 2;               // col quarter (n = q*32 + nt2*8)
    unsigned wA1[2][8][4];
#pragma unroll
    for (int r = 0; r < 2; ++r) {
        int rb = 2 * p + r;
#pragma unroll
        for (int jb = 0; jb < 8; ++jb) {
            int base = (rb * 16 + g) * 64 + jb * 8 + tq;
            wA1[r][jb][0] = g_W1u[base];
            wA1[r][jb][1] = g_W1u[base + 8 * 64];
            wA1[r][jb][2] = g_W1u[base + 4];
            wA1[r][jb][3] = g_W1u[base + 8 * 64 + 4];
        }
    }

    // ---- Phase A: build H (tf32) into B-frag layout (R10) ----
#pragma unroll
    for (int it = 0; it < 8; ++it) {
        int idx = tid + it * 512;       // 0..4095
        int n  = idx & 127;
        int qq = idx >> 7;              // 0..31
        int jb = qq >> 2, tqq = qq & 3;
        int j1 = jb * 8 + tqq, j2 = j1 + 4;
        int mi = n >> 6, k = n & 63;
        float b1 = B0n[(m0 + mi) * 64 + j1];
        float b2 = B0n[(m0 + mi) * 64 + j2];
        float h1 = fmaxf(A0n[j1 * 64 + k] + b1, 0.f);
        float h2 = fmaxf(A0n[j2 * 64 + k] + b2, 0.f);
        uint2 hv;
        hv.x = f2tf(h1);
        hv.y = f2tf(h2);
        *reinterpret_cast<uint2*>(sHs + (qq * HSTR + n) * 2) = hv;
    }
    __syncthreads();

    // ---- GEMM1: each B-frag load feeds BOTH row-blocks ----
    {
        const uint2* hb = reinterpret_cast<const uint2*>(sHs);
        if (p < 2) {
            // both row-blocks are skip rows
#pragma unroll
            for (int nt2 = 0; nt2 < 4; ++nt2) {
                int n = q * 32 + nt2 * 8;
                float d0[4] = {0.f, 0.f, 0.f, 0.f};
                float d1[4] = {0.f, 0.f, 0.f, 0.f};
#pragma unroll
                for (int jb = 0; jb < 8; ++jb) {
                    uint2 bv = hb[(jb * 4 + tq) * HSTR + n + g];
                    mma_tf32(d0, wA1[0][jb], bv.x, bv.y);
                    mma_tf32(d1, wA1[1][jb], bv.x, bv.y);
                }
                int ccol = n + 2 * tq;
                int k = ccol & 63;
#pragma unroll
                for (int r = 0; r < 2; ++r) {
                    const float* d = r ? d1 : d0;
                    int c = (2 * p + r) * 16 + g;
                    float2 t0v = *reinterpret_cast<const float2*>(TsN + c * 64 + k);
                    float2 t8v = *reinterpret_cast<const float2*>(TsN + (c + 8) * 64 + k);
                    *reinterpret_cast<float2*>(sSkip + c * 136 + ccol) =
                        make_float2(d[0] + t0v.x, d[1] + t0v.y);
                    *reinterpret_cast<float2*>(sSkip + (c + 8) * 136 + ccol) =
                        make_float2(d[2] + t8v.x, d[3] + t8v.y);
                }
            }
        } else {
            // both row-blocks are fcn1a rows -> H1 to sHs2
#pragma unroll
            for (int nt2 = 0; nt2 < 4; ++nt2) {
                int n = q * 32 + nt2 * 8;
                float d0[4] = {0.f, 0.f, 0.f, 0.f};
                float d1[4] = {0.f, 0.f, 0.f, 0.f};
#pragma unroll
                for (int jb = 0; jb < 8; ++jb) {
                    uint2 bv = hb[(jb * 4 + tq) * HSTR + n + g];
                    mma_tf32(d0, wA1[0][jb], bv.x, bv.y);
                    mma_tf32(d1, wA1[1][jb], bv.x, bv.y);
                }
                int ccol = n + 2 * tq;
                int k = ccol & 63;
#pragma unroll
                for (int r = 0; r < 2; ++r) {
                    const float* d = r ? d1 : d0;
                    int c  = (2 * (p - 2) + r) * 16 + g;
                    int c8 = c + 8;
                    int q0 = ((c  >> 3) << 2) + (c  & 3), s0 = (c  >> 2) & 1;
                    int q8 = ((c8 >> 3) << 2) + (c8 & 3), s8 = (c8 >> 2) & 1;
                    float2 a0v = *reinterpret_cast<const float2*>(TaN + c * 64 + k);
                    float2 a8v = *reinterpret_cast<const float2*>(TaN + c8 * 64 + k);
                    sHs2[(q0 * HSTR + ccol) * 2 + s0] =
                        f2tf(fmaxf(d[0] + a0v.x, 0.f));
                    sHs2[(q0 * HSTR + ccol + 1) * 2 + s0] =
                        f2tf(fmaxf(d[1] + a0v.y, 0.f));
                    sHs2[(q8 * HSTR + ccol) * 2 + s8] =
                        f2tf(fmaxf(d[2] + a8v.x, 0.f));
                    sHs2[(q8 * HSTR + ccol + 1) * 2 + s8] =
                        f2tf(fmaxf(d[3] + a8v.y, 0.f));
                }
            }
        }
    }

    // ---- GEMM2 A-fragments (two row-blocks) + biases ----
    const int p2 = w & 1;               // pair -> row-blocks 2p2, 2p2+1 (of 4)
    const int e8 = w >> 1;              // col eighth (n = e8*16 + nt2*8)
    unsigned wA2[2][8][4];
#pragma unroll
    for (int r = 0; r < 2; ++r) {
        int rb = 2 * p2 + r;
#pragma unroll
        for (int jb = 0; jb < 8; ++jb) {
            int base = (rb * 16 + g) * 64 + jb * 8 + tq;
            wA2[r][jb][0] = g_W2u[base];
            wA2[r][jb][1] = g_W2u[base + 8 * 64];
            wA2[r][jb][2] = g_W2u[base + 4];
            wA2[r][jb][3] = g_W2u[base + 8 * 64 + 4];
        }
    }
    float tbv[2][2];
#pragma unroll
    for (int r = 0; r < 2; ++r) {
        tbv[r][0] = g_t1b[(2 * p2 + r) * 16 + g];
        tbv[r][1] = g_t1b[(2 * p2 + r) * 16 + g + 8];
    }
    __syncthreads();   // H1 + sSkip complete

    // ---- GEMM2 + combine + k-max over this warp's 16 cols ----
    float mx[2][2] = {{-3.4e38f, -3.4e38f}, {-3.4e38f, -3.4e38f}};
    {
        const uint2* hb2 = reinterpret_cast<const uint2*>(sHs2);
#pragma unroll
        for (int nt2 = 0; nt2 < 2; ++nt2) {
            int n = e8 * 16 + nt2 * 8;
            float d0[4] = {tbv[0][0], tbv[0][0], tbv[0][1], tbv[0][1]};
            float d1[4] = {tbv[1][0], tbv[1][0], tbv[1][1], tbv[1][1]};
#pragma unroll
            for (int jb = 0; jb < 8; ++jb) {
                uint2 bv = hb2[(jb * 4 + tq) * HSTR + n + g];
                mma_tf32(d0, wA2[0][jb], bv.x, bv.y);
                mma_tf32(d1, wA2[1][jb], bv.x, bv.y);
            }
            int ccol = n + 2 * tq;
#pragma unroll
            for (int r = 0; r < 2; ++r) {
                const float* d = r ? d1 : d0;
                int c = (2 * p2 + r) * 16 + g;
                float2 sk0 = *reinterpret_cast<const float2*>(sSkip + c * 136 + ccol);
                float2 sk8 = *reinterpret_cast<const float2*>(sSkip + (c + 8) * 136 + ccol);
                float v0 = fmaxf(d[0], 0.f) + sk0.x;
                float v1 = fmaxf(d[1], 0.f) + sk0.y;
                float v2 = fmaxf(d[2], 0.f) + sk8.x;
                float v3 = fmaxf(d[3], 0.f) + sk8.y;
                mx[r][0] = fmaxf(mx[r][0], fmaxf(v0, v1));
                mx[r][1] = fmaxf(mx[r][1], fmaxf(v2, v3));
            }
        }
    }
#pragma unroll
    for (int r = 0; r < 2; ++r) {
#pragma unroll
        for (int h = 0; h < 2; ++h) {
            mx[r][h] = fmaxf(mx[r][h], __shfl_xor_sync(0xffffffffu, mx[r][h], 1));
            mx[r][h] = fmaxf(mx[r][h], __shfl_xor_sync(0xffffffffu, mx[r][h], 2));
        }
    }
    if (tq == 0) {
#pragma unroll
        for (int r = 0; r < 2; ++r) {
            int c = (2 * p2 + r) * 16 + g;
            sPM[c * 8 + e8]       = mx[r][0];
            sPM[(c + 8) * 8 + e8] = mx[r][1];
        }
    }
    __syncthreads();

    // ---- finalize max per (c, mi): eighths mi*4 .. mi*4+3 ----
    if (tid < 128) {
        int c = tid & 63, mi = tid >> 6;
        const float* row = sPM + c * 8 + mi * 4;
        sF[mi * 64 + c] = fmaxf(fmaxf(row[0], row[1]), fmaxf(row[2], row[3]));
    }
    __syncthreads();

    // ---- output: out[n][o][m] = Wout[o,:64]@sF + Wout[o,64:67]@pre_xyz ----
    if (w < 6) {
        const int fo_mi = w / 3, fo_o = w - fo_mi * 3;
        const float* pxn = pre_xyz + n_ * 3 * M_;
        int m = m0 + fo_mi;
        float pv = Wout[fo_o * 67 + lane] * sF[fo_mi * 64 + lane] +
                   Wout[fo_o * 67 + 32 + lane] * sF[fo_mi * 64 + 32 + lane];
#pragma unroll
        for (int off = 16; off >= 1; off >>= 1)
            pv += __shfl_xor_sync(0xffffffffu, pv, off);
        if (lane == 0) {
            pv += Wout[fo_o * 67 + 64] * pxn[m] +
                  Wout[fo_o * 67 + 65] * pxn[M_ + m] +
                  Wout[fo_o * 67 + 66] * pxn[2 * M_ + m];
            out[n_ * 3 * M_ + fo_o * M_ + m] = pv;
        }
    }
}

// ---------------- launcher ----------------
extern "C" void kernel_launch(void* const* d_in, const int* in_sizes, int n_in,
                              void* d_out, int out_size)
{
    const float* query     = (const float*)d_in[0];
    const float* scene_rgb = (const float*)d_in[1];
    const float* scene_xyz = (const float*)d_in[2];
    const float* pre_xyz   = (const float*)d_in[3];
    const float* mask      = (const float*)d_in[4];
    const float* W0        = (const float*)d_in[5];
    const float* g0        = (const float*)d_in[6];
    const float* b0        = (const float*)d_in[7];
    const float* m0        = (const float*)d_in[8];
    const float* v0        = (const float*)d_in[9];
    const float* W1a       = (const float*)d_in[10];
    const float* g1a       = (const float*)d_in[11];
    const float* b1a       = (const float*)d_in[12];
    const float* m1a       = (const float*)d_in[13];
    const float* v1a       = (const float*)d_in[14];
    const float* W1b       = (const float*)d_in[15];
    const float* g1b       = (const float*)d_in[16];
    const float* b1b       = (const float*)d_in[17];
    const float* m1b       = (const float*)d_in[18];
    const float* v1b       = (const float*)d_in[19];
    const float* Wskip     = (const float*)d_in[20];
    const float* Wout      = (const float*)d_in[21];
    float* out = (float*)d_out;

    prep_weights<<<1, 256>>>(W1a, W1b, Wskip,
                             g0, b0, m0, v0,
                             g1a, b1a, m1a, v1a,
                             g1b, b1b, m1b, v1b);
    prep_nk<<<(N_ * C_ * K_) / 256, 256>>>(scene_rgb, scene_xyz, mask,
                                           W0, W1a, Wskip);
    prep_B0t<<<N_ * 150, 128>>>(query, W0);

    cudaFuncSetAttribute(fused_main, cudaFuncAttributeMaxDynamicSharedMemorySize,
                         SMEM_FLOATS * 4);
    fused_main<<<N_ * (M_ / 2), 512, SMEM_FLOATS * 4>>>(pre_xyz, Wout, out);
}

// round 14
// speedup vs baseline: 1.5022x; 1.5022x over previous
#include <cuda_runtime.h>
#include <cstdint>

// Problem constants
#define N_ 2
#define C_ 64
#define M_ 4800
#define K_ 64
#define EPS_ 1e-5f

// ---------------- device scratch (no allocation allowed) ----------------
__device__ __align__(16) float g_B0t[N_ * M_ * C_];  // s0[c]*(W0q@query), [n][m][c]
__device__ __align__(16) float g_A0p[N_ * C_ * K_];  // s0*(W0s@scene)+t0  [n][j][k]
__device__ __align__(16) float g_Ts [N_ * C_ * K_];  // Wskip_xyz @ sx     [n][c][k]
__device__ __align__(16) float g_T1a[N_ * C_ * K_];  // s1a*(W1a_xyz@sx)+t1a [n][c][k]
// tf32 weight bit-patterns (row-major)
__device__ __align__(16) unsigned g_W1u[128 * 64];   // [Wskip ; s1a*W1a]
__device__ __align__(16) unsigned g_W2u[64 * 64];    // s1b*W1b
__device__ float g_t1b[C_];

// ---------------- helpers ----------------
__device__ __forceinline__ unsigned f2tf(float x) {
    unsigned u;
    asm("cvt.rna.tf32.f32 %0, %1;" : "=r"(u) : "f"(x));
    return u;
}

__device__ __forceinline__ void mma_tf32(float d[4], const unsigned a[4],
                                         unsigned b0, unsigned b1) {
    asm volatile(
        "mma.sync.aligned.m16n8k8.row.col.f32.tf32.tf32.f32 "
        "{%0,%1,%2,%3}, {%4,%5,%6,%7}, {%8,%9}, {%0,%1,%2,%3};"
        : "+f"(d[0]), "+f"(d[1]), "+f"(d[2]), "+f"(d[3])
        : "r"(a[0]), "r"(a[1]), "r"(a[2]), "r"(a[3]), "r"(b0), "r"(b1));
}

// ---------------- single fused prep kernel ----------------
// grid = 333 blocks x 256 threads, no inter-block dependencies (BN folds
// recomputed inline where needed):
//   block 0        : tf32 weight images + t1b
//   blocks 1..32   : per-(n,k) tensors A0p / Ts / T1a
//   blocks 33..332 : B0t transpose (N_*150 chunks of 32 m)
__global__ void __launch_bounds__(256) prep_all(
    const float* __restrict__ query,       // (N,C,M,1)
    const float* __restrict__ scene_rgb,   // (N,C,1,K)
    const float* __restrict__ scene_xyz,   // (N,3,1,K)
    const float* __restrict__ mask,        // (N,1,1,K)
    const float* __restrict__ W0,          // (C,2C)
    const float* __restrict__ W1a,         // (C,C+3)
    const float* __restrict__ W1b,         // (C,C)
    const float* __restrict__ Wskip,       // (C,C+3)
    const float* __restrict__ g0, const float* __restrict__ b0,
    const float* __restrict__ m0, const float* __restrict__ v0,
    const float* __restrict__ g1a, const float* __restrict__ b1a,
    const float* __restrict__ m1a, const float* __restrict__ v1a,
    const float* __restrict__ g1b, const float* __restrict__ b1b,
    const float* __restrict__ m1b, const float* __restrict__ v1b)
{
    const int bid = blockIdx.x;
    const int t   = threadIdx.x;

    if (bid == 0) {
        // ---- weight images ----
        __shared__ float s1a_s[C_], s1b_s[C_];
        if (t < C_) {
            float sa = g1a[t] * rsqrtf(v1a[t] + EPS_);
            s1a_s[t] = sa;
            float sb = g1b[t] * rsqrtf(v1b[t] + EPS_);
            s1b_s[t] = sb;
            g_t1b[t] = b1b[t] - m1b[t] * sb;
        }
        __syncthreads();
        for (int i = t; i < 128 * 64; i += 256) {
            int r = i >> 6, j = i & 63;
            float v1 = (r < 64) ? Wskip[r * 67 + j]
                                : s1a_s[r - 64] * W1a[(r - 64) * 67 + j];
            g_W1u[i] = f2tf(v1);
            if (r < 64)
                g_W2u[i] = f2tf(s1b_s[r] * W1b[r * 64 + j]);
        }
    } else if (bid <= 32) {
        // ---- per-(n,k) tensors ----
        int gid = (bid - 1) * 256 + t;     // 0 .. 8191
        int n = gid >> 12;
        int r = gid & 4095;
        int c = r >> 6;
        int k = r & 63;
        float s0  = g0[c] * rsqrtf(v0[c] + EPS_);
        float t0v = b0[c] - m0[c] * s0;
        float sa  = g1a[c] * rsqrtf(v1a[c] + EPS_);
        float t1v = b1a[c] - m1a[c] * sa;

        const float* sc = scene_rgb + n * C_ * K_;
        float acc = 0.f;
#pragma unroll 8
        for (int j = 0; j < C_; ++j)
            acc = fmaf(W0[c * 2 * C_ + j], sc[j * K_ + k], acc);
        g_A0p[gid] = s0 * acc + t0v;

        float mk = mask[n * K_ + k];
        float x0 = scene_xyz[n * 3 * K_ + 0 * K_ + k] * mk;
        float x1 = scene_xyz[n * 3 * K_ + 1 * K_ + k] * mk;
        float x2 = scene_xyz[n * 3 * K_ + 2 * K_ + k] * mk;
        g_Ts[gid]  = Wskip[c * 67 + 64] * x0 + Wskip[c * 67 + 65] * x1 +
                     Wskip[c * 67 + 66] * x2;
        g_T1a[gid] = sa * (W1a[c * 67 + 64] * x0 + W1a[c * 67 + 65] * x1 +
                           W1a[c * 67 + 66] * x2) + t1v;
    } else {
        // ---- B0t transpose (32-m chunk) ----
        __shared__ float sq[64 * 32];      // [j][ml]
        __shared__ float sw[64 * 64];      // [j][c]
        const int b2 = bid - 33;           // 0 .. 299
        const int n = b2 / 150;
        const int m0 = (b2 % 150) * 32;

        for (int i = t; i < 4096; i += 256) {
            int c = i >> 6, j = i & 63;
            sw[j * 64 + c] = W0[c * 2 * C_ + C_ + j];
        }
        const float* qn = query + n * C_ * M_;
        for (int i = t; i < 2048; i += 256) {
            int j = i >> 5, ml = i & 31;
            sq[i] = qn[j * M_ + m0 + ml];
        }
        __syncthreads();

        if (t < 128) {
            const int ml = t & 31;
            const int cg = t >> 5;         // 4 groups of 16 c
            float acc[16];
#pragma unroll
            for (int i = 0; i < 16; ++i) acc[i] = 0.f;
#pragma unroll 4
            for (int j = 0; j < 64; ++j) {
                float qv = sq[j * 32 + ml];
                const float4* wr =
                    reinterpret_cast<const float4*>(sw + j * 64 + cg * 16);
                float4 w0v = wr[0], w1v = wr[1], w2v = wr[2], w3v = wr[3];
                float wv[16] = {w0v.x, w0v.y, w0v.z, w0v.w,
                                w1v.x, w1v.y, w1v.z, w1v.w,
                                w2v.x, w2v.y, w2v.z, w2v.w,
                                w3v.x, w3v.y, w3v.z, w3v.w};
#pragma unroll
                for (int ci = 0; ci < 16; ++ci)
                    acc[ci] = fmaf(wv[ci], qv, acc[ci]);
            }
            float* outp = g_B0t + n * M_ * C_ + (m0 + ml) * C_ + cg * 16;
#pragma unroll
            for (int ci = 0; ci < 16; ++ci) {
                int c = cg * 16 + ci;
                float s0 = g0[c] * rsqrtf(v0[c] + EPS_);
                outp[ci] = acc[ci] * s0;
            }
        }
    }
}

// ---------------- fused main kernel (mma.sync tf32, 2 CTAs/SM) ----------------
// EXACT R10 champion configuration (264.7us kernel).
// 512 threads, CTA = one m-tile (Tm=2; n-cols = mi*64 + k, 128 total).
// H (and H1) stored as B-fragments: for j-block jb and in-block quad t,
// the pair (j = jb*8+t, j+4) interleaved at uint index ((jb*4+t)*132+n)*2+s.
// GEMM1: [Wskip; s1a*W1a](128x64j) @ H. Each nt-chain's d[4] is written back
// IMMEDIATELY (skip->sSkip(+Ts), fcn1a->relu(+T1a)->tf32->sHs2) -- no
// registers held across barriers -> 2 CTAs/SM for phase overlap.
// GEMM2: s1b*W1b(64x64c) @ H1 (from sHs2) + t1b, relu, +skip, k-max.
// smem floats: sHs 8448 | sHs2 8448 | sSkip 8704 | sPM 256 | sF 128
#define SHS_F  0
#define SHS2_F 8448
#define SSK_F  16896
#define SPM_F  25600
#define SF_F   25856
#define SMEM_FLOATS 25984

extern "C" __global__ void __launch_bounds__(512, 2) fused_main(
    const float* __restrict__ pre_xyz,   // (N,3,M)
    const float* __restrict__ Wout,      // (3,C+3)
    float* __restrict__ out)             // (N,3,M)
{
    extern __shared__ float smem[];
    unsigned* sHs   = reinterpret_cast<unsigned*>(smem + SHS_F);
    unsigned* sHs2  = reinterpret_cast<unsigned*>(smem + SHS2_F);
    float*    sSkip = smem + SSK_F;
    float*    sPM   = smem + SPM_F;
    float*    sF    = smem + SF_F;

    const int tid  = threadIdx.x;
    const int lane = tid & 31;
    const int w    = tid >> 5;          // 0..15
    const int g    = lane >> 2;         // fragment group 0..7
    const int tq   = lane & 3;          // fragment quad-thread 0..3

    const int t   = blockIdx.x;         // 0..4799
    const int n_  = t / (M_ / 2);
    const int m0  = (t % (M_ / 2)) * 2;

    const float* A0n = g_A0p + n_ * 4096;
    const float* B0n = g_B0t + n_ * M_ * C_;
    const float* TsN = g_Ts  + n_ * 4096;
    const float* TaN = g_T1a + n_ * 4096;

    // ---- GEMM1 A-fragments (registers, once) ----
    const int rb = w >> 1;              // row-block 0..7 (0-3 skip, 4-7 fcn1a)
    const int nh = w & 1;               // n-half
    unsigned wA1[8][4];
#pragma unroll
    for (int jb = 0; jb < 8; ++jb) {
        int base = (rb * 16 + g) * 64 + jb * 8 + tq;
        wA1[jb][0] = g_W1u[base];
        wA1[jb][1] = g_W1u[base + 8 * 64];
        wA1[jb][2] = g_W1u[base + 4];
        wA1[jb][3] = g_W1u[base + 8 * 64 + 4];
    }

    // ---- Phase A: build H (tf32) into B-frag layout ----
#pragma unroll
    for (int it = 0; it < 8; ++it) {
        int idx = tid + it * 512;       // 0..4095
        int n  = idx & 127;
        int q  = idx >> 7;              // 0..31
        int jb = q >> 2, tqq = q & 3;
        int j1 = jb * 8 + tqq, j2 = j1 + 4;
        int mi = n >> 6, k = n & 63;
        float b1 = B0n[(m0 + mi) * 64 + j1];
        float b2 = B0n[(m0 + mi) * 64 + j2];
        float h1 = fmaxf(A0n[j1 * 64 + k] + b1, 0.f);
        float h2 = fmaxf(A0n[j2 * 64 + k] + b2, 0.f);
        uint2 hv;
        hv.x = f2tf(h1);
        hv.y = f2tf(h2);
        *reinterpret_cast<uint2*>(sHs + (q * 132 + n) * 2) = hv;
    }
    __syncthreads();

    // ---- GEMM1 mma with immediate per-nt writeback ----
    {
        const uint2* hb = reinterpret_cast<const uint2*>(sHs);
        if (rb < 4) {
            // skip rows: c = rb*16+g (+8)
            const int c = rb * 16 + g;
#pragma unroll
            for (int nt = 0; nt < 8; ++nt) {
                int n = nh * 64 + nt * 8;
                float d[4] = {0.f, 0.f, 0.f, 0.f};
#pragma unroll
                for (int jb = 0; jb < 8; ++jb) {
                    uint2 bv = hb[(jb * 4 + tq) * 132 + n + g];
                    mma_tf32(d, wA1[jb], bv.x, bv.y);
                }
                int ccol = n + 2 * tq;
                int k = ccol & 63;
                float2 t0v = *reinterpret_cast<const float2*>(TsN + c * 64 + k);
                float2 t8v = *reinterpret_cast<const float2*>(TsN + (c + 8) * 64 + k);
                *reinterpret_cast<float2*>(sSkip + c * 136 + ccol) =
                    make_float2(d[0] + t0v.x, d[1] + t0v.y);
                *reinterpret_cast<float2*>(sSkip + (c + 8) * 136 + ccol) =
                    make_float2(d[2] + t8v.x, d[3] + t8v.y);
            }
        } else {
            // fcn1a rows: H1 = relu(v + T1a) -> tf32 -> sHs2 (B-frag layout)
            const int c  = (rb - 4) * 16 + g;
            const int c8 = c + 8;
            const int q0 = ((c  >> 3) << 2) + (c  & 3), s0 = (c  >> 2) & 1;
            const int q8 = ((c8 >> 3) << 2) + (c8 & 3), s8 = (c8 >> 2) & 1;
#pragma unroll
            for (int nt = 0; nt < 8; ++nt) {
                int n = nh * 64 + nt * 8;
                float d[4] = {0.f, 0.f, 0.f, 0.f};
#pragma unroll
                for (int jb = 0; jb < 8; ++jb) {
                    uint2 bv = hb[(jb * 4 + tq) * 132 + n + g];
                    mma_tf32(d, wA1[jb], bv.x, bv.y);
                }
                int ccol = n + 2 * tq;
                int k = ccol & 63;
                float2 a0v = *reinterpret_cast<const float2*>(TaN + c * 64 + k);
                float2 a8v = *reinterpret_cast<const float2*>(TaN + c8 * 64 + k);
                sHs2[(q0 * 132 + ccol) * 2 + s0] =
                    f2tf(fmaxf(d[0] + a0v.x, 0.f));
                sHs2[(q0 * 132 + ccol + 1) * 2 + s0] =
                    f2tf(fmaxf(d[1] + a0v.y, 0.f));
                sHs2[(q8 * 132 + ccol) * 2 + s8] =
                    f2tf(fmaxf(d[2] + a8v.x, 0.f));
                sHs2[(q8 * 132 + ccol + 1) * 2 + s8] =
                    f2tf(fmaxf(d[3] + a8v.y, 0.f));
            }
        }
    }

    // ---- GEMM2 A-fragments + bias (wA1 dead) ----
    const int rb2 = w & 3;
    const int qtr = w >> 2;             // n-quarter 0..3 (mi = qtr>>1)
    unsigned wA2[8][4];
#pragma unroll
    for (int jb = 0; jb < 8; ++jb) {
        int base = (rb2 * 16 + g) * 64 + jb * 8 + tq;
        wA2[jb][0] = g_W2u[base];
        wA2[jb][1] = g_W2u[base + 8 * 64];
        wA2[jb][2] = g_W2u[base + 4];
        wA2[jb][3] = g_W2u[base + 8 * 64 + 4];
    }
    const float t1bg  = g_t1b[rb2 * 16 + g];
    const float t1bg8 = g_t1b[rb2 * 16 + g + 8];
    __syncthreads();   // H1 + sSkip complete

    // ---- GEMM2 + combine + k-max ----
    float mxg = -3.4e38f, mxg8 = -3.4e38f;
    {
        const uint2* hb2 = reinterpret_cast<const uint2*>(sHs2);
        const int c = rb2 * 16 + g;
#pragma unroll
        for (int nt2 = 0; nt2 < 4; ++nt2) {
            int n = qtr * 32 + nt2 * 8;
            float d[4] = {t1bg, t1bg, t1bg8, t1bg8};
#pragma unroll
            for (int jb = 0; jb < 8; ++jb) {
                uint2 bv = hb2[(jb * 4 + tq) * 132 + n + g];
                mma_tf32(d, wA2[jb], bv.x, bv.y);
            }
            int ccol = n + 2 * tq;
            float2 sk0 = *reinterpret_cast<const float2*>(sSkip + c * 136 + ccol);
            float2 sk8 = *reinterpret_cast<const float2*>(sSkip + (c + 8) * 136 + ccol);
            float v0 = fmaxf(d[0], 0.f) + sk0.x;
            float v1 = fmaxf(d[1], 0.f) + sk0.y;
            float v2 = fmaxf(d[2], 0.f) + sk8.x;
            float v3 = fmaxf(d[3], 0.f) + sk8.y;
            mxg  = fmaxf(mxg,  fmaxf(v0, v1));
            mxg8 = fmaxf(mxg8, fmaxf(v2, v3));
        }
    }
    mxg  = fmaxf(mxg,  __shfl_xor_sync(0xffffffffu, mxg, 1));
    mxg  = fmaxf(mxg,  __shfl_xor_sync(0xffffffffu, mxg, 2));
    mxg8 = fmaxf(mxg8, __shfl_xor_sync(0xffffffffu, mxg8, 1));
    mxg8 = fmaxf(mxg8, __shfl_xor_sync(0xffffffffu, mxg8, 2));
    if (tq == 0) {
        sPM[(rb2 * 16 + g) * 4 + qtr]     = mxg;
        sPM[(rb2 * 16 + g + 8) * 4 + qtr] = mxg8;
    }
    __syncthreads();

    // ---- finalize max per (c, mi) ----
    if (tid < 128) {
        int c = tid & 63, mi = tid >> 6;
        sF[mi * 64 + c] = fmaxf(sPM[c * 4 + 2 * mi], sPM[c * 4 + 2 * mi + 1]);
    }
    __syncthreads();

    // ---- output: out[n][o][m] = Wout[o,:64]@sF + Wout[o,64:67]@pre_xyz ----
    if (w < 6) {
        const int fo_mi = w / 3, fo_o = w - fo_mi * 3;
        const float* pxn = pre_xyz + n_ * 3 * M_;
        int m = m0 + fo_mi;
        float p = Wout[fo_o * 67 + lane] * sF[fo_mi * 64 + lane] +
                  Wout[fo_o * 67 + 32 + lane] * sF[fo_mi * 64 + 32 + lane];
#pragma unroll
        for (int off = 16; off >= 1; off >>= 1)
            p += __shfl_xor_sync(0xffffffffu, p, off);
        if (lane == 0) {
            p += Wout[fo_o * 67 + 64] * pxn[m] +
                 Wout[fo_o * 67 + 65] * pxn[M_ + m] +
                 Wout[fo_o * 67 + 66] * pxn[2 * M_ + m];
            out[n_ * 3 * M_ + fo_o * M_ + m] = p;
        }
    }
}

// ---------------- launcher ----------------
extern "C" void kernel_launch(void* const* d_in, const int* in_sizes, int n_in,
                              void* d_out, int out_size)
{
    const float* query     = (const float*)d_in[0];
    const float* scene_rgb = (const float*)d_in[1];
    const float* scene_xyz = (const float*)d_in[2];
    const float* pre_xyz   = (const float*)d_in[3];
    const float* mask      = (const float*)d_in[4];
    const float* W0        = (const float*)d_in[5];
    const float* g0        = (const float*)d_in[6];
    const float* b0        = (const float*)d_in[7];
    const float* m0        = (const float*)d_in[8];
    const float* v0        = (const float*)d_in[9];
    const float* W1a       = (const float*)d_in[10];
    const float* g1a       = (const float*)d_in[11];
    const float* b1a       = (const float*)d_in[12];
    const float* m1a       = (const float*)d_in[13];
    const float* v1a       = (const float*)d_in[14];
    const float* W1b       = (const float*)d_in[15];
    const float* g1b       = (const float*)d_in[16];
    const float* b1b       = (const float*)d_in[17];
    const float* m1b       = (const float*)d_in[18];
    const float* v1b       = (const float*)d_in[19];
    const float* Wskip     = (const float*)d_in[20];
    const float* Wout      = (const float*)d_in[21];
    float* out = (float*)d_out;

    // one fused prep launch (no inter-kernel serialization)
    prep_all<<<333, 256>>>(query, scene_rgb, scene_xyz, mask,
                           W0, W1a, W1b, Wskip,
                           g0, b0, m0, v0,
                           g1a, b1a, m1a, v1a,
                           g1b, b1b, m1b, v1b);

    cudaFuncSetAttribute(fused_main, cudaFuncAttributeMaxDynamicSharedMemorySize,
                         SMEM_FLOATS * 4);
    fused_main<<<N_ * (M_ / 2), 512, SMEM_FLOATS * 4>>>(pre_xyz, Wout, out);
}

// round 15
// speedup vs baseline: 3.0112x; 2.0046x over previous
#include <cuda_runtime.h>
#include <cstdint>

// Problem constants
#define N_ 2
#define C_ 64
#define M_ 4800
#define K_ 64
#define EPS_ 1e-5f

// ---------------- device scratch (no allocation allowed) ----------------
__device__ __align__(16) float g_B0t[N_ * M_ * C_];  // s0[c]*(W0q@query), [n][m][c]
__device__ __align__(16) float g_A0p[N_ * C_ * K_];  // s0*(W0s@scene)+t0  [n][j][k]
// pre-swizzled constant fragments (exact per-thread load order)
__device__ __align__(16) uint4  g_W1f[8 * 8 * 32];   // [rb][jb][lane] GEMM1 A-frags
__device__ __align__(16) uint4  g_W2f[4 * 8 * 32];   // [rb2][jb][lane] GEMM2 A-frags
__device__ __align__(16) float4 g_Tsf[N_ * 4 * 8 * 32]; // [n][rb][nt][lane] skip bias
__device__ __align__(16) float4 g_Taf[N_ * 4 * 8 * 32]; // [n][rb][nt][lane] fcn1a bias
__device__ float g_t1b[C_];

// ---------------- helpers ----------------
__device__ __forceinline__ unsigned f2tf(float x) {
    unsigned u;
    asm("cvt.rna.tf32.f32 %0, %1;" : "=r"(u) : "f"(x));
    return u;
}

__device__ __forceinline__ void mma_tf32(float d[4], const unsigned a[4],
                                         unsigned b0, unsigned b1) {
    asm volatile(
        "mma.sync.aligned.m16n8k8.row.col.f32.tf32.tf32.f32 "
        "{%0,%1,%2,%3}, {%4,%5,%6,%7}, {%8,%9}, {%0,%1,%2,%3};"
        : "+f"(d[0]), "+f"(d[1]), "+f"(d[2]), "+f"(d[3])
        : "r"(a[0]), "r"(a[1]), "r"(a[2]), "r"(a[3]), "r"(b0), "r"(b1));
}

// ---------------- single fused prep kernel ----------------
// grid = 333 blocks x 256 threads, no inter-block dependencies:
//   block 0        : weight fragment tables (g_W1f/g_W2f) + t1b
//   blocks 1..32   : A0p + bias fragment tables (g_Tsf/g_Taf)
//   blocks 33..332 : B0t transpose (N_*150 chunks of 32 m)
__global__ void __launch_bounds__(256) prep_all(
    const float* __restrict__ query,       // (N,C,M,1)
    const float* __restrict__ scene_rgb,   // (N,C,1,K)
    const float* __restrict__ scene_xyz,   // (N,3,1,K)
    const float* __restrict__ mask,        // (N,1,1,K)
    const float* __restrict__ W0,          // (C,2C)
    const float* __restrict__ W1a,         // (C,C+3)
    const float* __restrict__ W1b,         // (C,C)
    const float* __restrict__ Wskip,       // (C,C+3)
    const float* __restrict__ g0, const float* __restrict__ b0,
    const float* __restrict__ m0, const float* __restrict__ v0,
    const float* __restrict__ g1a, const float* __restrict__ b1a,
    const float* __restrict__ m1a, const float* __restrict__ v1a,
    const float* __restrict__ g1b, const float* __restrict__ b1b,
    const float* __restrict__ m1b, const float* __restrict__ v1b)
{
    const int bid = blockIdx.x;
    const int t   = threadIdx.x;

    if (bid == 0) {
        // ---- weight fragment tables ----
        __shared__ float s1a_s[C_], s1b_s[C_];
        if (t < C_) {
            float sa = g1a[t] * rsqrtf(v1a[t] + EPS_);
            s1a_s[t] = sa;
            float sb = g1b[t] * rsqrtf(v1b[t] + EPS_);
            s1b_s[t] = sb;
            g_t1b[t] = b1b[t] - m1b[t] * sb;
        }
        __syncthreads();
        // v1(r,j) for the stacked [Wskip ; s1a*W1a] matrix (r in 0..127)
        auto v1 = [&](int r, int j) -> float {
            return (r < 64) ? Wskip[r * 67 + j]
                            : s1a_s[r - 64] * W1a[(r - 64) * 67 + j];
        };
        for (int i = t; i < 8 * 8 * 32; i += 256) {
            int lane = i & 31;
            int jb = (i >> 5) & 7;
            int rb = i >> 8;
            int g = lane >> 2, tq = lane & 3;
            int r = rb * 16 + g, j = jb * 8 + tq;
            uint4 v;
            v.x = f2tf(v1(r,     j));
            v.y = f2tf(v1(r + 8, j));
            v.z = f2tf(v1(r,     j + 4));
            v.w = f2tf(v1(r + 8, j + 4));
            g_W1f[i] = v;
        }
        for (int i = t; i < 4 * 8 * 32; i += 256) {
            int lane = i & 31;
            int jb = (i >> 5) & 7;
            int rb2 = i >> 8;
            int g = lane >> 2, tq = lane & 3;
            int c = rb2 * 16 + g, j = jb * 8 + tq;
            uint4 v;
            v.x = f2tf(s1b_s[c]     * W1b[c * 64 + j]);
            v.y = f2tf(s1b_s[c + 8] * W1b[(c + 8) * 64 + j]);
            v.z = f2tf(s1b_s[c]     * W1b[c * 64 + j + 4]);
            v.w = f2tf(s1b_s[c + 8] * W1b[(c + 8) * 64 + j + 4]);
            g_W2f[i] = v;
        }
    } else if (bid <= 32) {
        int gid = (bid - 1) * 256 + t;     // 0 .. 8191

        // ---- A0p (unchanged [n][j][k] layout) ----
        {
            int n = gid >> 12;
            int r = gid & 4095;
            int c = r >> 6;
            int k = r & 63;
            float s0  = g0[c] * rsqrtf(v0[c] + EPS_);
            float t0v = b0[c] - m0[c] * s0;
            const float* sc = scene_rgb + n * C_ * K_;
            float acc = 0.f;
#pragma unroll 8
            for (int j = 0; j < C_; ++j)
                acc = fmaf(W0[c * 2 * C_ + j], sc[j * K_ + k], acc);
            g_A0p[gid] = s0 * acc + t0v;
        }

        // ---- bias fragment tables (gid<4096: Ts; else: Ta) ----
        {
            int e = gid & 4095;
            int n = e >> 11;                // 1024 entries per n per table
            int r = e & 1023;
            int rb = r >> 8;
            int nt = (r >> 5) & 7;
            int lane = r & 31;
            int g = lane >> 2, tq = lane & 3;
            int c = rb * 16 + g;
            int k = nt * 8 + 2 * tq;

            // masked xyz at k and k+1
            float mk0 = mask[n * K_ + k];
            float mk1 = mask[n * K_ + k + 1];
            const float* xz = scene_xyz + n * 3 * K_;
            float x00 = xz[k] * mk0,          x01 = xz[k + 1] * mk1;
            float x10 = xz[K_ + k] * mk0,     x11 = xz[K_ + k + 1] * mk1;
            float x20 = xz[2 * K_ + k] * mk0, x21 = xz[2 * K_ + k + 1] * mk1;

            if (gid < 4096) {
                float w0c = Wskip[c * 67 + 64], w1c = Wskip[c * 67 + 65],
                      w2c = Wskip[c * 67 + 66];
                int c8 = c + 8;
                float w08 = Wskip[c8 * 67 + 64], w18 = Wskip[c8 * 67 + 65],
                      w28 = Wskip[c8 * 67 + 66];
                float4 v;
                v.x = w0c * x00 + w1c * x10 + w2c * x20;
                v.y = w0c * x01 + w1c * x11 + w2c * x21;
                v.z = w08 * x00 + w18 * x10 + w28 * x20;
                v.w = w08 * x01 + w18 * x11 + w28 * x21;
                g_Tsf[((n * 4 + rb) * 8 + nt) * 32 + lane] = v;
            } else {
                float sac = g1a[c] * rsqrtf(v1a[c] + EPS_);
                float tac = b1a[c] - m1a[c] * sac;
                int c8 = c + 8;
                float sa8 = g1a[c8] * rsqrtf(v1a[c8] + EPS_);
                float ta8 = b1a[c8] - m1a[c8] * sa8;
                float w0c = W1a[c * 67 + 64], w1c = W1a[c * 67 + 65],
                      w2c = W1a[c * 67 + 66];
                float w08 = W1a[c8 * 67 + 64], w18 = W1a[c8 * 67 + 65],
                      w28 = W1a[c8 * 67 + 66];
                float4 v;
                v.x = sac * (w0c * x00 + w1c * x10 + w2c * x20) + tac;
                v.y = sac * (w0c * x01 + w1c * x11 + w2c * x21) + tac;
                v.z = sa8 * (w08 * x00 + w18 * x10 + w28 * x20) + ta8;
                v.w = sa8 * (w08 * x01 + w18 * x11 + w28 * x21) + ta8;
                g_Taf[((n * 4 + rb) * 8 + nt) * 32 + lane] = v;
            }
        }
    } else {
        // ---- B0t transpose (32-m chunk) ----
        __shared__ float sq[64 * 32];      // [j][ml]
        __shared__ float sw[64 * 64];      // [j][c]
        const int b2 = bid - 33;           // 0 .. 299
        const int n = b2 / 150;
        const int m0 = (b2 % 150) * 32;

        for (int i = t; i < 4096; i += 256) {
            int c = i >> 6, j = i & 63;
            sw[j * 64 + c] = W0[c * 2 * C_ + C_ + j];
        }
        const float* qn = query + n * C_ * M_;
        for (int i = t; i < 2048; i += 256) {
            int j = i >> 5, ml = i & 31;
            sq[i] = qn[j * M_ + m0 + ml];
        }
        __syncthreads();

        if (t < 128) {
            const int ml = t & 31;
            const int cg = t >> 5;
            float acc[16];
#pragma unroll
            for (int i = 0; i < 16; ++i) acc[i] = 0.f;
#pragma unroll 4
            for (int j = 0; j < 64; ++j) {
                float qv = sq[j * 32 + ml];
                const float4* wr =
                    reinterpret_cast<const float4*>(sw + j * 64 + cg * 16);
                float4 w0v = wr[0], w1v = wr[1], w2v = wr[2], w3v = wr[3];
                float wv[16] = {w0v.x, w0v.y, w0v.z, w0v.w,
                                w1v.x, w1v.y, w1v.z, w1v.w,
                                w2v.x, w2v.y, w2v.z, w2v.w,
                                w3v.x, w3v.y, w3v.z, w3v.w};
#pragma unroll
                for (int ci = 0; ci < 16; ++ci)
                    acc[ci] = fmaf(wv[ci], qv, acc[ci]);
            }
            float* outp = g_B0t + n * M_ * C_ + (m0 + ml) * C_ + cg * 16;
#pragma unroll
            for (int ci = 0; ci < 16; ++ci) {
                int c = cg * 16 + ci;
                float s0 = g0[c] * rsqrtf(v0[c] + EPS_);
                outp[ci] = acc[ci] * s0;
            }
        }
    }
}

// ---------------- fused main kernel (mma.sync tf32, 2 CTAs/SM) ----------------
// R10 champion structure; all constant fragments now loaded from pre-swizzled
// tables with fully-coalesced LDG.128 (addresses changed, math identical).
// smem floats: sHs 8448 | sHs2 8448 | sSkip 8704 | sPM 256 | sF 128
#define SHS_F  0
#define SHS2_F 8448
#define SSK_F  16896
#define SPM_F  25600
#define SF_F   25856
#define SMEM_FLOATS 25984

extern "C" __global__ void __launch_bounds__(512, 2) fused_main(
    const float* __restrict__ pre_xyz,   // (N,3,M)
    const float* __restrict__ Wout,      // (3,C+3)
    float* __restrict__ out)             // (N,3,M)
{
    extern __shared__ float smem[];
    unsigned* sHs   = reinterpret_cast<unsigned*>(smem + SHS_F);
    unsigned* sHs2  = reinterpret_cast<unsigned*>(smem + SHS2_F);
    float*    sSkip = smem + SSK_F;
    float*    sPM   = smem + SPM_F;
    float*    sF    = smem + SF_F;

    const int tid  = threadIdx.x;
    const int lane = tid & 31;
    const int w    = tid >> 5;          // 0..15
    const int g    = lane >> 2;         // fragment group 0..7
    const int tq   = lane & 3;          // fragment quad-thread 0..3

    const int t   = blockIdx.x;         // 0..4799
    const int n_  = t / (M_ / 2);
    const int m0  = (t % (M_ / 2)) * 2;

    const float* A0n = g_A0p + n_ * 4096;
    const float* B0n = g_B0t + n_ * M_ * C_;

    // ---- GEMM1 A-fragments: coalesced LDG.128 from pre-swizzled table ----
    const int rb = w >> 1;              // row-block 0..7 (0-3 skip, 4-7 fcn1a)
    const int nh = w & 1;               // n-half
    unsigned wA1[8][4];
#pragma unroll
    for (int jb = 0; jb < 8; ++jb) {
        uint4 v = g_W1f[(rb * 8 + jb) * 32 + lane];
        wA1[jb][0] = v.x; wA1[jb][1] = v.y;
        wA1[jb][2] = v.z; wA1[jb][3] = v.w;
    }

    // ---- Phase A: build H (tf32) into B-frag layout ----
#pragma unroll
    for (int it = 0; it < 8; ++it) {
        int idx = tid + it * 512;       // 0..4095
        int n  = idx & 127;
        int q  = idx >> 7;              // 0..31
        int jb = q >> 2, tqq = q & 3;
        int j1 = jb * 8 + tqq, j2 = j1 + 4;
        int mi = n >> 6, k = n & 63;
        float b1 = B0n[(m0 + mi) * 64 + j1];
        float b2 = B0n[(m0 + mi) * 64 + j2];
        float h1 = fmaxf(A0n[j1 * 64 + k] + b1, 0.f);
        float h2 = fmaxf(A0n[j2 * 64 + k] + b2, 0.f);
        uint2 hv;
        hv.x = f2tf(h1);
        hv.y = f2tf(h2);
        *reinterpret_cast<uint2*>(sHs + (q * 132 + n) * 2) = hv;
    }
    __syncthreads();

    // ---- GEMM1 mma with immediate per-nt writeback ----
    {
        const uint2* hb = reinterpret_cast<const uint2*>(sHs);
        if (rb < 4) {
            // skip rows: c = rb*16+g (+8)
            const int c = rb * 16 + g;
            const float4* tsf = g_Tsf + (n_ * 4 + rb) * 8 * 32 + lane;
#pragma unroll
            for (int nt = 0; nt < 8; ++nt) {
                int n = nh * 64 + nt * 8;
                float d[4] = {0.f, 0.f, 0.f, 0.f};
#pragma unroll
                for (int jb = 0; jb < 8; ++jb) {
                    uint2 bv = hb[(jb * 4 + tq) * 132 + n + g];
                    mma_tf32(d, wA1[jb], bv.x, bv.y);
                }
                int ccol = n + 2 * tq;
                float4 tv = tsf[nt * 32];   // {Ts(c,k),Ts(c,k+1),Ts(c+8,k),Ts(c+8,k+1)}
                *reinterpret_cast<float2*>(sSkip + c * 136 + ccol) =
                    make_float2(d[0] + tv.x, d[1] + tv.y);
                *reinterpret_cast<float2*>(sSkip + (c + 8) * 136 + ccol) =
                    make_float2(d[2] + tv.z, d[3] + tv.w);
            }
        } else {
            // fcn1a rows: H1 = relu(v + T1a) -> tf32 -> sHs2 (B-frag layout)
            const int c  = (rb - 4) * 16 + g;
            const int c8 = c + 8;
            const int q0 = ((c  >> 3) << 2) + (c  & 3), s0 = (c  >> 2) & 1;
            const int q8 = ((c8 >> 3) << 2) + (c8 & 3), s8 = (c8 >> 2) & 1;
            const float4* taf = g_Taf + (n_ * 4 + (rb - 4)) * 8 * 32 + lane;
#pragma unroll
            for (int nt = 0; nt < 8; ++nt) {
                int n = nh * 64 + nt * 8;
                float d[4] = {0.f, 0.f, 0.f, 0.f};
#pragma unroll
                for (int jb = 0; jb < 8; ++jb) {
                    uint2 bv = hb[(jb * 4 + tq) * 132 + n + g];
                    mma_tf32(d, wA1[jb], bv.x, bv.y);
                }
                int ccol = n + 2 * tq;
                float4 av = taf[nt * 32];   // {Ta(c,k),Ta(c,k+1),Ta(c+8,k),Ta(c+8,k+1)}
                sHs2[(q0 * 132 + ccol) * 2 + s0] =
                    f2tf(fmaxf(d[0] + av.x, 0.f));
                sHs2[(q0 * 132 + ccol + 1) * 2 + s0] =
                    f2tf(fmaxf(d[1] + av.y, 0.f));
                sHs2[(q8 * 132 + ccol) * 2 + s8] =
                    f2tf(fmaxf(d[2] + av.z, 0.f));
                sHs2[(q8 * 132 + ccol + 1) * 2 + s8] =
                    f2tf(fmaxf(d[3] + av.w, 0.f));
            }
        }
    }

    // ---- GEMM2 A-fragments + bias (wA1 dead) ----
    const int rb2 = w & 3;
    const int qtr = w >> 2;             // n-quarter 0..3 (mi = qtr>>1)
    unsigned wA2[8][4];
#pragma unroll
    for (int jb = 0; jb < 8; ++jb) {
        uint4 v = g_W2f[(rb2 * 8 + jb) * 32 + lane];
        wA2[jb][0] = v.x; wA2[jb][1] = v.y;
        wA2[jb][2] = v.z; wA2[jb][3] = v.w;
    }
    const float t1bg  = g_t1b[rb2 * 16 + g];
    const float t1bg8 = g_t1b[rb2 * 16 + g + 8];
    __syncthreads();   // H1 + sSkip complete

    // ---- GEMM2 + combine + k-max ----
    float mxg = -3.4e38f, mxg8 = -3.4e38f;
    {
        const uint2* hb2 = reinterpret_cast<const uint2*>(sHs2);
        const int c = rb2 * 16 + g;
#pragma unroll
        for (int nt2 = 0; nt2 < 4; ++nt2) {
            int n = qtr * 32 + nt2 * 8;
            float d[4] = {t1bg, t1bg, t1bg8, t1bg8};
#pragma unroll
            for (int jb = 0; jb < 8; ++jb) {
                uint2 bv = hb2[(jb * 4 + tq) * 132 + n + g];
                mma_tf32(d, wA2[jb], bv.x, bv.y);
            }
            int ccol = n + 2 * tq;
            float2 sk0 = *reinterpret_cast<const float2*>(sSkip + c * 136 + ccol);
            float2 sk8 = *reinterpret_cast<const float2*>(sSkip + (c + 8) * 136 + ccol);
            float v0 = fmaxf(d[0], 0.f) + sk0.x;
            float v1 = fmaxf(d[1], 0.f) + sk0.y;
            float v2 = fmaxf(d[2], 0.f) + sk8.x;
            float v3 = fmaxf(d[3], 0.f) + sk8.y;
            mxg  = fmaxf(mxg,  fmaxf(v0, v1));
            mxg8 = fmaxf(mxg8, fmaxf(v2, v3));
        }
    }
    mxg  = fmaxf(mxg,  __shfl_xor_sync(0xffffffffu, mxg, 1));
    mxg  = fmaxf(mxg,  __shfl_xor_sync(0xffffffffu, mxg, 2));
    mxg8 = fmaxf(mxg8, __shfl_xor_sync(0xffffffffu, mxg8, 1));
    mxg8 = fmaxf(mxg8, __shfl_xor_sync(0xffffffffu, mxg8, 2));
    if (tq == 0) {
        sPM[(rb2 * 16 + g) * 4 + qtr]     = mxg;
        sPM[(rb2 * 16 + g + 8) * 4 + qtr] = mxg8;
    }
    __syncthreads();

    // ---- finalize max per (c, mi) ----
    if (tid < 128) {
        int c = tid & 63, mi = tid >> 6;
        sF[mi * 64 + c] = fmaxf(sPM[c * 4 + 2 * mi], sPM[c * 4 + 2 * mi + 1]);
    }
    __syncthreads();

    // ---- output: out[n][o][m] = Wout[o,:64]@sF + Wout[o,64:67]@pre_xyz ----
    if (w < 6) {
        const int fo_mi = w / 3, fo_o = w - fo_mi * 3;
        const float* pxn = pre_xyz + n_ * 3 * M_;
        int m = m0 + fo_mi;
        float p = Wout[fo_o * 67 + lane] * sF[fo_mi * 64 + lane] +
                  Wout[fo_o * 67 + 32 + lane] * sF[fo_mi * 64 + 32 + lane];
#pragma unroll
        for (int off = 16; off >= 1; off >>= 1)
            p += __shfl_xor_sync(0xffffffffu, p, off);
        if (lane == 0) {
            p += Wout[fo_o * 67 + 64] * pxn[m] +
                 Wout[fo_o * 67 + 65] * pxn[M_ + m] +
                 Wout[fo_o * 67 + 66] * pxn[2 * M_ + m];
            out[n_ * 3 * M_ + fo_o * M_ + m] = p;
        }
    }
}

// ---------------- launcher ----------------
extern "C" void kernel_launch(void* const* d_in, const int* in_sizes, int n_in,
                              void* d_out, int out_size)
{
    const float* query     = (const float*)d_in[0];
    const float* scene_rgb = (const float*)d_in[1];
    const float* scene_xyz = (const float*)d_in[2];
    const float* pre_xyz   = (const float*)d_in[3];
    const float* mask      = (const float*)d_in[4];
    const float* W0        = (const float*)d_in[5];
    const float* g0        = (const float*)d_in[6];
    const float* b0        = (const float*)d_in[7];
    const float* m0        = (const float*)d_in[8];
    const float* v0        = (const float*)d_in[9];
    const float* W1a       = (const float*)d_in[10];
    const float* g1a       = (const float*)d_in[11];
    const float* b1a       = (const float*)d_in[12];
    const float* m1a       = (const float*)d_in[13];
    const float* v1a       = (const float*)d_in[14];
    const float* W1b       = (const float*)d_in[15];
    const float* g1b       = (const float*)d_in[16];
    const float* b1b       = (const float*)d_in[17];
    const float* m1b       = (const float*)d_in[18];
    const float* v1b       = (const float*)d_in[19];
    const float* Wskip     = (const float*)d_in[20];
    const float* Wout      = (const float*)d_in[21];
    float* out = (float*)d_out;

    prep_all<<<333, 256>>>(query, scene_rgb, scene_xyz, mask,
                           W0, W1a, W1b, Wskip,
                           g0, b0, m0, v0,
                           g1a, b1a, m1a, v1a,
                           g1b, b1b, m1b, v1b);

    cudaFuncSetAttribute(fused_main, cudaFuncAttributeMaxDynamicSharedMemorySize,
                         SMEM_FLOATS * 4);
    fused_main<<<N_ * (M_ / 2), 512, SMEM_FLOATS * 4>>>(pre_xyz, Wout, out);
}

// round 16
// speedup vs baseline: 3.0271x; 1.0053x over previous
#include <cuda_runtime.h>
#include <cstdint>

// Problem constants
#define N_ 2
#define C_ 64
#define M_ 4800
#define K_ 64
#define EPS_ 1e-5f

// ---------------- device scratch (no allocation allowed) ----------------
__device__ __align__(16) float g_B0t[N_ * M_ * C_];  // s0[c]*(W0q@query), [n][m][c]
__device__ __align__(16) float g_A0p[N_ * C_ * K_];  // s0*(W0s@scene)+t0  [n][j][k]
// pre-swizzled constant fragments (exact per-thread load order)
__device__ __align__(16) uint4  g_W1f[8 * 8 * 32];   // [rb][jb][lane] GEMM1 A-frags
__device__ __align__(16) uint4  g_W2f[4 * 8 * 32];   // [rb2][jb][lane] GEMM2 A-frags
__device__ __align__(16) float4 g_Tsf[N_ * 4 * 8 * 32]; // [n][rb][nt][lane] skip bias
__device__ __align__(16) float4 g_Taf[N_ * 4 * 8 * 32]; // [n][rb][nt][lane] fcn1a bias
__device__ float g_t1b[C_];

// ---------------- helpers ----------------
__device__ __forceinline__ unsigned f2tf(float x) {
    unsigned u;
    asm("cvt.rna.tf32.f32 %0, %1;" : "=r"(u) : "f"(x));
    return u;
}

__device__ __forceinline__ void mma_tf32(float d[4], const unsigned a[4],
                                         unsigned b0, unsigned b1) {
    asm volatile(
        "mma.sync.aligned.m16n8k8.row.col.f32.tf32.tf32.f32 "
        "{%0,%1,%2,%3}, {%4,%5,%6,%7}, {%8,%9}, {%0,%1,%2,%3};"
        : "+f"(d[0]), "+f"(d[1]), "+f"(d[2]), "+f"(d[3])
        : "r"(a[0]), "r"(a[1]), "r"(a[2]), "r"(a[3]), "r"(b0), "r"(b1));
}

// ---------------- single fused prep kernel ----------------
// grid = 333 blocks x 256 threads, no inter-block dependencies:
//   block 0        : weight fragment tables (g_W1f/g_W2f) + t1b
//   blocks 1..32   : A0p + bias fragment tables (g_Tsf/g_Taf)
//   blocks 33..332 : B0t transpose (N_*150 chunks of 32 m, ALL 256 threads)
__global__ void __launch_bounds__(256) prep_all(
    const float* __restrict__ query,       // (N,C,M,1)
    const float* __restrict__ scene_rgb,   // (N,C,1,K)
    const float* __restrict__ scene_xyz,   // (N,3,1,K)
    const float* __restrict__ mask,        // (N,1,1,K)
    const float* __restrict__ W0,          // (C,2C)
    const float* __restrict__ W1a,         // (C,C+3)
    const float* __restrict__ W1b,         // (C,C)
    const float* __restrict__ Wskip,       // (C,C+3)
    const float* __restrict__ g0, const float* __restrict__ b0,
    const float* __restrict__ m0, const float* __restrict__ v0,
    const float* __restrict__ g1a, const float* __restrict__ b1a,
    const float* __restrict__ m1a, const float* __restrict__ v1a,
    const float* __restrict__ g1b, const float* __restrict__ b1b,
    const float* __restrict__ m1b, const float* __restrict__ v1b)
{
    const int bid = blockIdx.x;
    const int t   = threadIdx.x;

    if (bid == 0) {
        // ---- weight fragment tables ----
        __shared__ float s1a_s[C_], s1b_s[C_];
        if (t < C_) {
            float sa = g1a[t] * rsqrtf(v1a[t] + EPS_);
            s1a_s[t] = sa;
            float sb = g1b[t] * rsqrtf(v1b[t] + EPS_);
            s1b_s[t] = sb;
            g_t1b[t] = b1b[t] - m1b[t] * sb;
        }
        __syncthreads();
        auto v1 = [&](int r, int j) -> float {
            return (r < 64) ? Wskip[r * 67 + j]
                            : s1a_s[r - 64] * W1a[(r - 64) * 67 + j];
        };
        for (int i = t; i < 8 * 8 * 32; i += 256) {
            int lane = i & 31;
            int jb = (i >> 5) & 7;
            int rb = i >> 8;
            int g = lane >> 2, tq = lane & 3;
            int r = rb * 16 + g, j = jb * 8 + tq;
            uint4 v;
            v.x = f2tf(v1(r,     j));
            v.y = f2tf(v1(r + 8, j));
            v.z = f2tf(v1(r,     j + 4));
            v.w = f2tf(v1(r + 8, j + 4));
            g_W1f[i] = v;
        }
        for (int i = t; i < 4 * 8 * 32; i += 256) {
            int lane = i & 31;
            int jb = (i >> 5) & 7;
            int rb2 = i >> 8;
            int g = lane >> 2, tq = lane & 3;
            int c = rb2 * 16 + g, j = jb * 8 + tq;
            uint4 v;
            v.x = f2tf(s1b_s[c]     * W1b[c * 64 + j]);
            v.y = f2tf(s1b_s[c + 8] * W1b[(c + 8) * 64 + j]);
            v.z = f2tf(s1b_s[c]     * W1b[c * 64 + j + 4]);
            v.w = f2tf(s1b_s[c + 8] * W1b[(c + 8) * 64 + j + 4]);
            g_W2f[i] = v;
        }
    } else if (bid <= 32) {
        int gid = (bid - 1) * 256 + t;     // 0 .. 8191

        // ---- A0p ----
        {
            int n = gid >> 12;
            int r = gid & 4095;
            int c = r >> 6;
            int k = r & 63;
            float s0  = g0[c] * rsqrtf(v0[c] + EPS_);
            float t0v = b0[c] - m0[c] * s0;
            const float* sc = scene_rgb + n * C_ * K_;
            float acc = 0.f;
#pragma unroll 8
            for (int j = 0; j < C_; ++j)
                acc = fmaf(W0[c * 2 * C_ + j], sc[j * K_ + k], acc);
            g_A0p[gid] = s0 * acc + t0v;
        }

        // ---- bias fragment tables (gid<4096: Ts; else: Ta) ----
        {
            int e = gid & 4095;
            int n = e >> 11;
            int r = e & 1023;
            int rb = r >> 8;
            int nt = (r >> 5) & 7;
            int lane = r & 31;
            int g = lane >> 2, tq = lane & 3;
            int c = rb * 16 + g;
            int k = nt * 8 + 2 * tq;

            float mk0 = mask[n * K_ + k];
            float mk1 = mask[n * K_ + k + 1];
            const float* xz = scene_xyz + n * 3 * K_;
            float x00 = xz[k] * mk0,          x01 = xz[k + 1] * mk1;
            float x10 = xz[K_ + k] * mk0,     x11 = xz[K_ + k + 1] * mk1;
            float x20 = xz[2 * K_ + k] * mk0, x21 = xz[2 * K_ + k + 1] * mk1;

            if (gid < 4096) {
                float w0c = Wskip[c * 67 + 64], w1c = Wskip[c * 67 + 65],
                      w2c = Wskip[c * 67 + 66];
                int c8 = c + 8;
                float w08 = Wskip[c8 * 67 + 64], w18 = Wskip[c8 * 67 + 65],
                      w28 = Wskip[c8 * 67 + 66];
                float4 v;
                v.x = w0c * x00 + w1c * x10 + w2c * x20;
                v.y = w0c * x01 + w1c * x11 + w2c * x21;
                v.z = w08 * x00 + w18 * x10 + w28 * x20;
                v.w = w08 * x01 + w18 * x11 + w28 * x21;
                g_Tsf[((n * 4 + rb) * 8 + nt) * 32 + lane] = v;
            } else {
                float sac = g1a[c] * rsqrtf(v1a[c] + EPS_);
                float tac = b1a[c] - m1a[c] * sac;
                int c8 = c + 8;
                float sa8 = g1a[c8] * rsqrtf(v1a[c8] + EPS_);
                float ta8 = b1a[c8] - m1a[c8] * sa8;
                float w0c = W1a[c * 67 + 64], w1c = W1a[c * 67 + 65],
                      w2c = W1a[c * 67 + 66];
                float w08 = W1a[c8 * 67 + 64], w18 = W1a[c8 * 67 + 65],
                      w28 = W1a[c8 * 67 + 66];
                float4 v;
                v.x = sac * (w0c * x00 + w1c * x10 + w2c * x20) + tac;
                v.y = sac * (w0c * x01 + w1c * x11 + w2c * x21) + tac;
                v.z = sa8 * (w08 * x00 + w18 * x10 + w28 * x20) + ta8;
                v.w = sa8 * (w08 * x01 + w18 * x11 + w28 * x21) + ta8;
                g_Taf[((n * 4 + rb) * 8 + nt) * 32 + lane] = v;
            }
        }
    } else {
        // ---- B0t transpose (32-m chunk), ALL 256 threads compute ----
        __shared__ float sq[64 * 32];      // [j][ml]
        __shared__ float sw[64 * 64];      // [j][c]
        const int b2 = bid - 33;           // 0 .. 299
        const int n = b2 / 150;
        const int m0 = (b2 % 150) * 32;

        for (int i = t; i < 4096; i += 256) {
            int c = i >> 6, j = i & 63;
            sw[j * 64 + c] = W0[c * 2 * C_ + C_ + j];
        }
        const float* qn = query + n * C_ * M_;
        for (int i = t; i < 2048; i += 256) {
            int j = i >> 5, ml = i & 31;
            sq[i] = qn[j * M_ + m0 + ml];
        }
        __syncthreads();

        const int ml = t & 31;
        const int cg = t >> 5;             // 8 groups of 8 c
        float acc[8];
#pragma unroll
        for (int i = 0; i < 8; ++i) acc[i] = 0.f;
#pragma unroll 4
        for (int j = 0; j < 64; ++j) {
            float qv = sq[j * 32 + ml];
            const float4* wr =
                reinterpret_cast<const float4*>(sw + j * 64 + cg * 8);
            float4 w0v = wr[0], w1v = wr[1];
            float wv[8] = {w0v.x, w0v.y, w0v.z, w0v.w,
                           w1v.x, w1v.y, w1v.z, w1v.w};
#pragma unroll
            for (int ci = 0; ci < 8; ++ci)
                acc[ci] = fmaf(wv[ci], qv, acc[ci]);
        }
        float* outp = g_B0t + n * M_ * C_ + (m0 + ml) * C_ + cg * 8;
#pragma unroll
        for (int ci = 0; ci < 8; ++ci) {
            int c = cg * 8 + ci;
            float s0 = g0[c] * rsqrtf(v0[c] + EPS_);
            outp[ci] = acc[ci] * s0;
        }
    }
}

// ---------------- fused main kernel (mma.sync tf32, 2 CTAs/SM) ----------------
// R15 champion; inner loops rewritten with affine base pointers so the
// B-fragment LDS and writeback STS use immediate offsets (math identical).
// smem floats: sHs 8448 | sHs2 8448 | sSkip 8704 | sPM 256 | sF 128
#define SHS_F  0
#define SHS2_F 8448
#define SSK_F  16896
#define SPM_F  25600
#define SF_F   25856
#define SMEM_FLOATS 25984

extern "C" __global__ void __launch_bounds__(512, 2) fused_main(
    const float* __restrict__ pre_xyz,   // (N,3,M)
    const float* __restrict__ Wout,      // (3,C+3)
    float* __restrict__ out)             // (N,3,M)
{
    extern __shared__ float smem[];
    unsigned* sHs   = reinterpret_cast<unsigned*>(smem + SHS_F);
    unsigned* sHs2  = reinterpret_cast<unsigned*>(smem + SHS2_F);
    float*    sSkip = smem + SSK_F;
    float*    sPM   = smem + SPM_F;
    float*    sF    = smem + SF_F;

    const int tid  = threadIdx.x;
    const int lane = tid & 31;
    const int w    = tid >> 5;          // 0..15
    const int g    = lane >> 2;         // fragment group 0..7
    const int tq   = lane & 3;          // fragment quad-thread 0..3

    const int t   = blockIdx.x;         // 0..4799
    const int n_  = t / (M_ / 2);
    const int m0  = (t % (M_ / 2)) * 2;

    const float* A0n = g_A0p + n_ * 4096;
    const float* B0n = g_B0t + n_ * M_ * C_;

    // ---- GEMM1 A-fragments: coalesced LDG.128 from pre-swizzled table ----
    const int rb = w >> 1;              // row-block 0..7 (0-3 skip, 4-7 fcn1a)
    const int nh = w & 1;               // n-half
    unsigned wA1[8][4];
#pragma unroll
    for (int jb = 0; jb < 8; ++jb) {
        uint4 v = g_W1f[(rb * 8 + jb) * 32 + lane];
        wA1[jb][0] = v.x; wA1[jb][1] = v.y;
        wA1[jb][2] = v.z; wA1[jb][3] = v.w;
    }

    // per-warp affine base pointer for B-fragment loads
    const uint2* hrow1 = reinterpret_cast<const uint2*>(sHs) + tq * 132 + g;

    // ---- Phase A: build H (tf32) into B-frag layout ----
#pragma unroll
    for (int it = 0; it < 8; ++it) {
        int idx = tid + it * 512;       // 0..4095
        int n  = idx & 127;
        int q  = idx >> 7;              // 0..31
        int jb = q >> 2, tqq = q & 3;
        int j1 = jb * 8 + tqq, j2 = j1 + 4;
        int mi = n >> 6, k = n & 63;
        float b1 = B0n[(m0 + mi) * 64 + j1];
        float b2 = B0n[(m0 + mi) * 64 + j2];
        float h1 = fmaxf(A0n[j1 * 64 + k] + b1, 0.f);
        float h2 = fmaxf(A0n[j2 * 64 + k] + b2, 0.f);
        uint2 hv;
        hv.x = f2tf(h1);
        hv.y = f2tf(h2);
        *reinterpret_cast<uint2*>(sHs + (q * 132 + n) * 2) = hv;
    }
    __syncthreads();

    // ---- GEMM1 mma with immediate per-nt writeback ----
    {
        if (rb < 4) {
            // skip rows: c = rb*16+g (+8)
            const int c = rb * 16 + g;
            const float4* tsf = g_Tsf + (n_ * 4 + rb) * 8 * 32 + lane;
            float* skp0 = sSkip + c * 136 + nh * 64 + 2 * tq;
            float* skp8 = skp0 + 8 * 136;
            const uint2* hp0 = hrow1 + nh * 64;
#pragma unroll
            for (int nt = 0; nt < 8; ++nt) {
                const uint2* hp = hp0 + nt * 8;
                float d[4] = {0.f, 0.f, 0.f, 0.f};
#pragma unroll
                for (int jb = 0; jb < 8; ++jb) {
                    uint2 bv = hp[jb * 528];
                    mma_tf32(d, wA1[jb], bv.x, bv.y);
                }
                float4 tv = tsf[nt * 32];
                *reinterpret_cast<float2*>(skp0 + nt * 8) =
                    make_float2(d[0] + tv.x, d[1] + tv.y);
                *reinterpret_cast<float2*>(skp8 + nt * 8) =
                    make_float2(d[2] + tv.z, d[3] + tv.w);
            }
        } else {
            // fcn1a rows: H1 = relu(v + T1a) -> tf32 -> sHs2 (B-frag layout)
            const int c  = (rb - 4) * 16 + g;
            const int c8 = c + 8;
            const int q0 = ((c  >> 3) << 2) + (c  & 3), s0 = (c  >> 2) & 1;
            const int q8 = ((c8 >> 3) << 2) + (c8 & 3), s8 = (c8 >> 2) & 1;
            const float4* taf = g_Taf + (n_ * 4 + (rb - 4)) * 8 * 32 + lane;
            unsigned* h2p0 = sHs2 + q0 * 264 + (nh * 64 + 2 * tq) * 2 + s0;
            unsigned* h2p8 = sHs2 + q8 * 264 + (nh * 64 + 2 * tq) * 2 + s8;
            const uint2* hp0 = hrow1 + nh * 64;
#pragma unroll
            for (int nt = 0; nt < 8; ++nt) {
                const uint2* hp = hp0 + nt * 8;
                float d[4] = {0.f, 0.f, 0.f, 0.f};
#pragma unroll
                for (int jb = 0; jb < 8; ++jb) {
                    uint2 bv = hp[jb * 528];
                    mma_tf32(d, wA1[jb], bv.x, bv.y);
                }
                float4 av = taf[nt * 32];
                h2p0[nt * 16]     = f2tf(fmaxf(d[0] + av.x, 0.f));
                h2p0[nt * 16 + 2] = f2tf(fmaxf(d[1] + av.y, 0.f));
                h2p8[nt * 16]     = f2tf(fmaxf(d[2] + av.z, 0.f));
                h2p8[nt * 16 + 2] = f2tf(fmaxf(d[3] + av.w, 0.f));
            }
        }
    }

    // ---- GEMM2 A-fragments + bias (wA1 dead) ----
    const int rb2 = w & 3;
    const int qtr = w >> 2;             // n-quarter 0..3 (mi = qtr>>1)
    unsigned wA2[8][4];
#pragma unroll
    for (int jb = 0; jb < 8; ++jb) {
        uint4 v = g_W2f[(rb2 * 8 + jb) * 32 + lane];
        wA2[jb][0] = v.x; wA2[jb][1] = v.y;
        wA2[jb][2] = v.z; wA2[jb][3] = v.w;
    }
    const float t1bg  = g_t1b[rb2 * 16 + g];
    const float t1bg8 = g_t1b[rb2 * 16 + g + 8];
    __syncthreads();   // H1 + sSkip complete

    // ---- GEMM2 + combine + k-max ----
    float mxg = -3.4e38f, mxg8 = -3.4e38f;
    {
        const int c = rb2 * 16 + g;
        const uint2* hp0 =
            reinterpret_cast<const uint2*>(sHs2) + tq * 132 + g + qtr * 32;
        const float* skr0 = sSkip + c * 136 + qtr * 32 + 2 * tq;
        const float* skr8 = skr0 + 8 * 136;
#pragma unroll
        for (int nt2 = 0; nt2 < 4; ++nt2) {
            const uint2* hp = hp0 + nt2 * 8;
            float d[4] = {t1bg, t1bg, t1bg8, t1bg8};
#pragma unroll
            for (int jb = 0; jb < 8; ++jb) {
                uint2 bv = hp[jb * 528];
                mma_tf32(d, wA2[jb], bv.x, bv.y);
            }
            float2 sk0 = *reinterpret_cast<const float2*>(skr0 + nt2 * 8);
            float2 sk8 = *reinterpret_cast<const float2*>(skr8 + nt2 * 8);
            float v0 = fmaxf(d[0], 0.f) + sk0.x;
            float v1 = fmaxf(d[1], 0.f) + sk0.y;
            float v2 = fmaxf(d[2], 0.f) + sk8.x;
            float v3 = fmaxf(d[3], 0.f) + sk8.y;
            mxg  = fmaxf(mxg,  fmaxf(v0, v1));
            mxg8 = fmaxf(mxg8, fmaxf(v2, v3));
        }
    }
    mxg  = fmaxf(mxg,  __shfl_xor_sync(0xffffffffu, mxg, 1));
    mxg  = fmaxf(mxg,  __shfl_xor_sync(0xffffffffu, mxg, 2));
    mxg8 = fmaxf(mxg8, __shfl_xor_sync(0xffffffffu, mxg8, 1));
    mxg8 = fmaxf(mxg8, __shfl_xor_sync(0xffffffffu, mxg8, 2));
    if (tq == 0) {
        sPM[(rb2 * 16 + g) * 4 + qtr]     = mxg;
        sPM[(rb2 * 16 + g + 8) * 4 + qtr] = mxg8;
    }
    __syncthreads();

    // ---- finalize max per (c, mi) ----
    if (tid < 128) {
        int c = tid & 63, mi = tid >> 6;
        sF[mi * 64 + c] = fmaxf(sPM[c * 4 + 2 * mi], sPM[c * 4 + 2 * mi + 1]);
    }
    __syncthreads();

    // ---- output: out[n][o][m] = Wout[o,:64]@sF + Wout[o,64:67]@pre_xyz ----
    if (w < 6) {
        const int fo_mi = w / 3, fo_o = w - fo_mi * 3;
        const float* pxn = pre_xyz + n_ * 3 * M_;
        int m = m0 + fo_mi;
        float p = Wout[fo_o * 67 + lane] * sF[fo_mi * 64 + lane] +
                  Wout[fo_o * 67 + 32 + lane] * sF[fo_mi * 64 + 32 + lane];
#pragma unroll
        for (int off = 16; off >= 1; off >>= 1)
            p += __shfl_xor_sync(0xffffffffu, p, off);
        if (lane == 0) {
            p += Wout[fo_o * 67 + 64] * pxn[m] +
                 Wout[fo_o * 67 + 65] * pxn[M_ + m] +
                 Wout[fo_o * 67 + 66] * pxn[2 * M_ + m];
            out[n_ * 3 * M_ + fo_o * M_ + m] = p;
        }
    }
}

// ---------------- launcher ----------------
extern "C" void kernel_launch(void* const* d_in, const int* in_sizes, int n_in,
                              void* d_out, int out_size)
{
    const float* query     = (const float*)d_in[0];
    const float* scene_rgb = (const float*)d_in[1];
    const float* scene_xyz = (const float*)d_in[2];
    const float* pre_xyz   = (const float*)d_in[3];
    const float* mask      = (const float*)d_in[4];
    const float* W0        = (const float*)d_in[5];
    const float* g0        = (const float*)d_in[6];
    const float* b0        = (const float*)d_in[7];
    const float* m0        = (const float*)d_in[8];
    const float* v0        = (const float*)d_in[9];
    const float* W1a       = (const float*)d_in[10];
    const float* g1a       = (const float*)d_in[11];
    const float* b1a       = (const float*)d_in[12];
    const float* m1a       = (const float*)d_in[13];
    const float* v1a       = (const float*)d_in[14];
    const float* W1b       = (const float*)d_in[15];
    const float* g1b       = (const float*)d_in[16];
    const float* b1b       = (const float*)d_in[17];
    const float* m1b       = (const float*)d_in[18];
    const float* v1b       = (const float*)d_in[19];
    const float* Wskip     = (const float*)d_in[20];
    const float* Wout      = (const float*)d_in[21];
    float* out = (float*)d_out;

    prep_all<<<333, 256>>>(query, scene_rgb, scene_xyz, mask,
                           W0, W1a, W1b, Wskip,
                           g0, b0, m0, v0,
                           g1a, b1a, m1a, v1a,
                           g1b, b1b, m1b, v1b);

    cudaFuncSetAttribute(fused_main, cudaFuncAttributeMaxDynamicSharedMemorySize,
                         SMEM_FLOATS * 4);
    fused_main<<<N_ * (M_ / 2), 512, SMEM_FLOATS * 4>>>(pre_xyz, Wout, out);
}

// round 17
// speedup vs baseline: 4.2842x; 1.4153x over previous
#include <cuda_runtime.h>
#include <cuda_fp16.h>
#include <cstdint>

// Problem constants
#define N_ 2
#define C_ 64
#define M_ 4800
#define K_ 64
#define EPS_ 1e-5f

// ---------------- device scratch (no allocation allowed) ----------------
__device__ __align__(16) float g_B0t[N_ * M_ * C_];  // s0[c]*(W0q@query), [n][m][c]
__device__ __align__(16) float g_A0p[N_ * C_ * K_];  // s0*(W0s@scene)+t0  [n][j][k]
// pre-swizzled constant fragments (exact per-thread load order, fp16 pairs)
__device__ __align__(16) uint4  g_W1f[8 * 4 * 32];   // [rb][jb][lane] GEMM1 A-frags
__device__ __align__(16) uint4  g_W2f[4 * 4 * 32];   // [rb2][jb][lane] GEMM2 A-frags
__device__ __align__(16) float4 g_Tsf[N_ * 4 * 8 * 32]; // [n][rb][nt][lane] skip bias
__device__ __align__(16) float4 g_Taf[N_ * 4 * 8 * 32]; // [n][rb][nt][lane] fcn1a bias
__device__ float g_t1b[C_];

// ---------------- helpers ----------------
// pack two f32 into f16x2: low half = lo, high half = hi
__device__ __forceinline__ unsigned pack_h2(float lo, float hi) {
    unsigned r;
    asm("cvt.rn.f16x2.f32 %0, %1, %2;" : "=r"(r) : "f"(hi), "f"(lo));
    return r;
}

__device__ __forceinline__ void mma_f16(float d[4], const unsigned a[4],
                                        unsigned b0, unsigned b1) {
    asm volatile(
        "mma.sync.aligned.m16n8k16.row.col.f32.f16.f16.f32 "
        "{%0,%1,%2,%3}, {%4,%5,%6,%7}, {%8,%9}, {%0,%1,%2,%3};"
        : "+f"(d[0]), "+f"(d[1]), "+f"(d[2]), "+f"(d[3])
        : "r"(a[0]), "r"(a[1]), "r"(a[2]), "r"(a[3]), "r"(b0), "r"(b1));
}

// ---------------- single fused prep kernel ----------------
// grid = 333 blocks x 256 threads, no inter-block dependencies:
//   block 0        : fp16 weight fragment tables (g_W1f/g_W2f) + t1b
//   blocks 1..32   : A0p + bias fragment tables (g_Tsf/g_Taf)
//   blocks 33..332 : B0t transpose (N_*150 chunks of 32 m, all 256 threads)
__global__ void __launch_bounds__(256) prep_all(
    const float* __restrict__ query,       // (N,C,M,1)
    const float* __restrict__ scene_rgb,   // (N,C,1,K)
    const float* __restrict__ scene_xyz,   // (N,3,1,K)
    const float* __restrict__ mask,        // (N,1,1,K)
    const float* __restrict__ W0,          // (C,2C)
    const float* __restrict__ W1a,         // (C,C+3)
    const float* __restrict__ W1b,         // (C,C)
    const float* __restrict__ Wskip,       // (C,C+3)
    const float* __restrict__ g0, const float* __restrict__ b0,
    const float* __restrict__ m0, const float* __restrict__ v0,
    const float* __restrict__ g1a, const float* __restrict__ b1a,
    const float* __restrict__ m1a, const float* __restrict__ v1a,
    const float* __restrict__ g1b, const float* __restrict__ b1b,
    const float* __restrict__ m1b, const float* __restrict__ v1b)
{
    const int bid = blockIdx.x;
    const int t   = threadIdx.x;

    if (bid == 0) {
        // ---- fp16 weight fragment tables ----
        __shared__ float s1a_s[C_], s1b_s[C_];
        if (t < C_) {
            float sa = g1a[t] * rsqrtf(v1a[t] + EPS_);
            s1a_s[t] = sa;
            float sb = g1b[t] * rsqrtf(v1b[t] + EPS_);
            s1b_s[t] = sb;
            g_t1b[t] = b1b[t] - m1b[t] * sb;
        }
        __syncthreads();
        auto v1 = [&](int r, int j) -> float {
            return (r < 64) ? Wskip[r * 67 + j]
                            : s1a_s[r - 64] * W1a[(r - 64) * 67 + j];
        };
        // GEMM1: m16n8k16 A-frag = 4 f16x2 regs
        for (int i = t; i < 8 * 4 * 32; i += 256) {
            int lane = i & 31;
            int jb = (i >> 5) & 3;
            int rb = i >> 7;
            int g = lane >> 2, tq = lane & 3;
            int r = rb * 16 + g, j0 = jb * 16 + 2 * tq;
            uint4 v;
            v.x = pack_h2(v1(r,     j0),     v1(r,     j0 + 1));
            v.y = pack_h2(v1(r + 8, j0),     v1(r + 8, j0 + 1));
            v.z = pack_h2(v1(r,     j0 + 8), v1(r,     j0 + 9));
            v.w = pack_h2(v1(r + 8, j0 + 8), v1(r + 8, j0 + 9));
            g_W1f[i] = v;
        }
        auto v2 = [&](int c, int j) -> float {
            return s1b_s[c] * W1b[c * 64 + j];
        };
        for (int i = t; i < 4 * 4 * 32; i += 256) {
            int lane = i & 31;
            int jb = (i >> 5) & 3;
            int rb2 = i >> 7;
            int g = lane >> 2, tq = lane & 3;
            int c = rb2 * 16 + g, j0 = jb * 16 + 2 * tq;
            uint4 v;
            v.x = pack_h2(v2(c,     j0),     v2(c,     j0 + 1));
            v.y = pack_h2(v2(c + 8, j0),     v2(c + 8, j0 + 1));
            v.z = pack_h2(v2(c,     j0 + 8), v2(c,     j0 + 9));
            v.w = pack_h2(v2(c + 8, j0 + 8), v2(c + 8, j0 + 9));
            g_W2f[i] = v;
        }
    } else if (bid <= 32) {
        int gid = (bid - 1) * 256 + t;     // 0 .. 8191

        // ---- A0p ----
        {
            int n = gid >> 12;
            int r = gid & 4095;
            int c = r >> 6;
            int k = r & 63;
            float s0  = g0[c] * rsqrtf(v0[c] + EPS_);
            float t0v = b0[c] - m0[c] * s0;
            const float* sc = scene_rgb + n * C_ * K_;
            float acc = 0.f;
#pragma unroll 8
            for (int j = 0; j < C_; ++j)
                acc = fmaf(W0[c * 2 * C_ + j], sc[j * K_ + k], acc);
            g_A0p[gid] = s0 * acc + t0v;
        }

        // ---- bias fragment tables (gid<4096: Ts; else: Ta) ----
        {
            int e = gid & 4095;
            int n = e >> 11;
            int r = e & 1023;
            int rb = r >> 8;
            int nt = (r >> 5) & 7;
            int lane = r & 31;
            int g = lane >> 2, tq = lane & 3;
            int c = rb * 16 + g;
            int k = nt * 8 + 2 * tq;

            float mk0 = mask[n * K_ + k];
            float mk1 = mask[n * K_ + k + 1];
            const float* xz = scene_xyz + n * 3 * K_;
            float x00 = xz[k] * mk0,          x01 = xz[k + 1] * mk1;
            float x10 = xz[K_ + k] * mk0,     x11 = xz[K_ + k + 1] * mk1;
            float x20 = xz[2 * K_ + k] * mk0, x21 = xz[2 * K_ + k + 1] * mk1;

            if (gid < 4096) {
                float w0c = Wskip[c * 67 + 64], w1c = Wskip[c * 67 + 65],
                      w2c = Wskip[c * 67 + 66];
                int c8 = c + 8;
                float w08 = Wskip[c8 * 67 + 64], w18 = Wskip[c8 * 67 + 65],
                      w28 = Wskip[c8 * 67 + 66];
                float4 v;
                v.x = w0c * x00 + w1c * x10 + w2c * x20;
                v.y = w0c * x01 + w1c * x11 + w2c * x21;
                v.z = w08 * x00 + w18 * x10 + w28 * x20;
                v.w = w08 * x01 + w18 * x11 + w28 * x21;
                g_Tsf[((n * 4 + rb) * 8 + nt) * 32 + lane] = v;
            } else {
                float sac = g1a[c] * rsqrtf(v1a[c] + EPS_);
                float tac = b1a[c] - m1a[c] * sac;
                int c8 = c + 8;
                float sa8 = g1a[c8] * rsqrtf(v1a[c8] + EPS_);
                float ta8 = b1a[c8] - m1a[c8] * sa8;
                float w0c = W1a[c * 67 + 64], w1c = W1a[c * 67 + 65],
                      w2c = W1a[c * 67 + 66];
                float w08 = W1a[c8 * 67 + 64], w18 = W1a[c8 * 67 + 65],
                      w28 = W1a[c8 * 67 + 66];
                float4 v;
                v.x = sac * (w0c * x00 + w1c * x10 + w2c * x20) + tac;
                v.y = sac * (w0c * x01 + w1c * x11 + w2c * x21) + tac;
                v.z = sa8 * (w08 * x00 + w18 * x10 + w28 * x20) + ta8;
                v.w = sa8 * (w08 * x01 + w18 * x11 + w28 * x21) + ta8;
                g_Taf[((n * 4 + rb) * 8 + nt) * 32 + lane] = v;
            }
        }
    } else {
        // ---- B0t transpose (32-m chunk), all 256 threads compute ----
        __shared__ float sq[64 * 32];      // [j][ml]
        __shared__ float sw[64 * 64];      // [j][c]
        const int b2 = bid - 33;           // 0 .. 299
        const int n = b2 / 150;
        const int m0 = (b2 % 150) * 32;

        for (int i = t; i < 4096; i += 256) {
            int c = i >> 6, j = i & 63;
            sw[j * 64 + c] = W0[c * 2 * C_ + C_ + j];
        }
        const float* qn = query + n * C_ * M_;
        for (int i = t; i < 2048; i += 256) {
            int j = i >> 5, ml = i & 31;
            sq[i] = qn[j * M_ + m0 + ml];
        }
        __syncthreads();

        const int ml = t & 31;
        const int cg = t >> 5;             // 8 groups of 8 c
        float acc[8];
#pragma unroll
        for (int i = 0; i < 8; ++i) acc[i] = 0.f;
#pragma unroll 4
        for (int j = 0; j < 64; ++j) {
            float qv = sq[j * 32 + ml];
            const float4* wr =
                reinterpret_cast<const float4*>(sw + j * 64 + cg * 8);
            float4 w0v = wr[0], w1v = wr[1];
            float wv[8] = {w0v.x, w0v.y, w0v.z, w0v.w,
                           w1v.x, w1v.y, w1v.z, w1v.w};
#pragma unroll
            for (int ci = 0; ci < 8; ++ci)
                acc[ci] = fmaf(wv[ci], qv, acc[ci]);
        }
        float* outp = g_B0t + n * M_ * C_ + (m0 + ml) * C_ + cg * 8;
#pragma unroll
        for (int ci = 0; ci < 8; ++ci) {
            int c = cg * 8 + ci;
            float s0 = g0[c] * rsqrtf(v0[c] + EPS_);
            outp[ci] = acc[ci] * s0;
        }
    }
}

// ---------------- fused main kernel (mma.sync fp16 m16n8k16, 2 CTAs/SM) ----
// Structure = R15 champion, datatype fp16 (same 11-bit mantissa as tf32):
// mma count, B-fragment loads, and H/H1 bytes all HALVED.
// H B-frag layout: quad-row q = jb*4 + tq (jb = 16-j block), col n holds
// uint2 = 4 packed halves for rows {16jb+2tq, +1, +8, +9}.
// smem floats: sHs 4224 | sHs2 4224 | sSkip 8704 | sPM 256 | sF 128
#define SHS_F  0
#define SHS2_F 4224
#define SSK_F  8448
#define SPM_F  17152
#define SF_F   17408
#define SMEM_FLOATS 17536

extern "C" __global__ void __launch_bounds__(512, 2) fused_main(
    const float* __restrict__ pre_xyz,   // (N,3,M)
    const float* __restrict__ Wout,      // (3,C+3)
    float* __restrict__ out)             // (N,3,M)
{
    extern __shared__ float smem[];
    unsigned* sHs   = reinterpret_cast<unsigned*>(smem + SHS_F);
    __half*   sH2h  = reinterpret_cast<__half*>(smem + SHS2_F);
    float*    sSkip = smem + SSK_F;
    float*    sPM   = smem + SPM_F;
    float*    sF    = smem + SF_F;

    const int tid  = threadIdx.x;
    const int lane = tid & 31;
    const int w    = tid >> 5;          // 0..15
    const int g    = lane >> 2;         // fragment group 0..7
    const int tq   = lane & 3;          // fragment quad-thread 0..3

    const int t   = blockIdx.x;         // 0..4799
    const int n_  = t / (M_ / 2);
    const int m0  = (t % (M_ / 2)) * 2;

    const float* A0n = g_A0p + n_ * 4096;
    const float* B0n = g_B0t + n_ * M_ * C_;

    // ---- GEMM1 A-fragments: 4 coalesced LDG.128 ----
    const int rb = w >> 1;              // row-block 0..7 (0-3 skip, 4-7 fcn1a)
    const int nh = w & 1;               // n-half
    unsigned wA1[4][4];
#pragma unroll
    for (int jb = 0; jb < 4; ++jb) {
        uint4 v = g_W1f[(rb * 4 + jb) * 32 + lane];
        wA1[jb][0] = v.x; wA1[jb][1] = v.y;
        wA1[jb][2] = v.z; wA1[jb][3] = v.w;
    }

    // ---- Phase A: build H (fp16) into B-frag layout ----
#pragma unroll
    for (int it = 0; it < 4; ++it) {
        int idx = tid + it * 512;       // 0..2047
        int n  = idx & 127;
        int q  = idx >> 7;              // 0..15
        int jb = q >> 2, tqq = q & 3;
        int j1 = jb * 16 + 2 * tqq;     // rows j1, j1+1, j1+8, j1+9
        int mi = n >> 6, k = n & 63;
        const float* Bm = B0n + (m0 + mi) * 64;
        float h0 = fmaxf(A0n[(j1    ) * 64 + k] + Bm[j1    ], 0.f);
        float h1 = fmaxf(A0n[(j1 + 1) * 64 + k] + Bm[j1 + 1], 0.f);
        float h8 = fmaxf(A0n[(j1 + 8) * 64 + k] + Bm[j1 + 8], 0.f);
        float h9 = fmaxf(A0n[(j1 + 9) * 64 + k] + Bm[j1 + 9], 0.f);
        uint2 hv;
        hv.x = pack_h2(h0, h1);
        hv.y = pack_h2(h8, h9);
        *reinterpret_cast<uint2*>(sHs + (q * 132 + n) * 2) = hv;
    }
    __syncthreads();

    // ---- GEMM1 mma with immediate per-nt writeback ----
    {
        const uint2* hrow1 =
            reinterpret_cast<const uint2*>(sHs) + tq * 132 + g + nh * 64;
        if (rb < 4) {
            // skip rows: c = rb*16+g (+8)
            const int c = rb * 16 + g;
            const float4* tsf = g_Tsf + (n_ * 4 + rb) * 8 * 32 + lane;
            float* skp0 = sSkip + c * 136 + nh * 64 + 2 * tq;
            float* skp8 = skp0 + 8 * 136;
#pragma unroll
            for (int nt = 0; nt < 8; ++nt) {
                const uint2* hp = hrow1 + nt * 8;
                float d[4] = {0.f, 0.f, 0.f, 0.f};
#pragma unroll
                for (int jb = 0; jb < 4; ++jb) {
                    uint2 bv = hp[jb * 528];
                    mma_f16(d, wA1[jb], bv.x, bv.y);
                }
                float4 tv = tsf[nt * 32];
                *reinterpret_cast<float2*>(skp0 + nt * 8) =
                    make_float2(d[0] + tv.x, d[1] + tv.y);
                *reinterpret_cast<float2*>(skp8 + nt * 8) =
                    make_float2(d[2] + tv.z, d[3] + tv.w);
            }
        } else {
            // fcn1a rows: H1 = relu(v + T1a) -> fp16 -> sHs2 (B-frag layout)
            // c = (rb-4)*16 + g; row c -> (q2, sub), row c+8 -> (q2, sub+2)
            const int jb2 = rb - 4;
            const int q2  = jb2 * 4 + (g >> 1);
            const int s   = g & 1;
            const float4* taf = g_Taf + (n_ * 4 + jb2) * 8 * 32 + lane;
            __half* hb0 = sH2h + (q2 * 132 + nh * 64 + 2 * tq) * 4 + s;
#pragma unroll
            for (int nt = 0; nt < 8; ++nt) {
                const uint2* hp = hrow1 + nt * 8;
                float d[4] = {0.f, 0.f, 0.f, 0.f};
#pragma unroll
                for (int jb = 0; jb < 4; ++jb) {
                    uint2 bv = hp[jb * 528];
                    mma_f16(d, wA1[jb], bv.x, bv.y);
                }
                float4 av = taf[nt * 32];
                __half* hw = hb0 + nt * 32;      // nt*8 cols * 4 halves
                hw[0]     = __float2half_rn(fmaxf(d[0] + av.x, 0.f));
                hw[4]     = __float2half_rn(fmaxf(d[1] + av.y, 0.f));
                hw[2]     = __float2half_rn(fmaxf(d[2] + av.z, 0.f));
                hw[6]     = __float2half_rn(fmaxf(d[3] + av.w, 0.f));
            }
        }
    }

    // ---- GEMM2 A-fragments + bias (wA1 dead) ----
    const int rb2 = w & 3;
    const int qtr = w >> 2;             // n-quarter 0..3 (mi = qtr>>1)
    unsigned wA2[4][4];
#pragma unroll
    for (int jb = 0; jb < 4; ++jb) {
        uint4 v = g_W2f[(rb2 * 4 + jb) * 32 + lane];
        wA2[jb][0] = v.x; wA2[jb][1] = v.y;
        wA2[jb][2] = v.z; wA2[jb][3] = v.w;
    }
    const float t1bg  = g_t1b[rb2 * 16 + g];
    const float t1bg8 = g_t1b[rb2 * 16 + g + 8];
    __syncthreads();   // H1 + sSkip complete

    // ---- GEMM2 + combine + k-max ----
    float mxg = -3.4e38f, mxg8 = -3.4e38f;
    {
        const int c = rb2 * 16 + g;
        const uint2* hp0 = reinterpret_cast<const uint2*>(smem + SHS2_F) +
                           tq * 132 + g + qtr * 32;
        const float* skr0 = sSkip + c * 136 + qtr * 32 + 2 * tq;
        const float* skr8 = skr0 + 8 * 136;
#pragma unroll
        for (int nt2 = 0; nt2 < 4; ++nt2) {
            const uint2* hp = hp0 + nt2 * 8;
            float d[4] = {t1bg, t1bg, t1bg8, t1bg8};
#pragma unroll
            for (int jb = 0; jb < 4; ++jb) {
                uint2 bv = hp[jb * 528];
                mma_f16(d, wA2[jb], bv.x, bv.y);
            }
            float2 sk0 = *reinterpret_cast<const float2*>(skr0 + nt2 * 8);
            float2 sk8 = *reinterpret_cast<const float2*>(skr8 + nt2 * 8);
            float v0 = fmaxf(d[0], 0.f) + sk0.x;
            float v1 = fmaxf(d[1], 0.f) + sk0.y;
            float v2 = fmaxf(d[2], 0.f) + sk8.x;
            float v3 = fmaxf(d[3], 0.f) + sk8.y;
            mxg  = fmaxf(mxg,  fmaxf(v0, v1));
            mxg8 = fmaxf(mxg8, fmaxf(v2, v3));
        }
    }
    mxg  = fmaxf(mxg,  __shfl_xor_sync(0xffffffffu, mxg, 1));
    mxg  = fmaxf(mxg,  __shfl_xor_sync(0xffffffffu, mxg, 2));
    mxg8 = fmaxf(mxg8, __shfl_xor_sync(0xffffffffu, mxg8, 1));
    mxg8 = fmaxf(mxg8, __shfl_xor_sync(0xffffffffu, mxg8, 2));
    if (tq == 0) {
        sPM[(rb2 * 16 + g) * 4 + qtr]     = mxg;
        sPM[(rb2 * 16 + g + 8) * 4 + qtr] = mxg8;
    }
    __syncthreads();

    // ---- finalize max per (c, mi) ----
    if (tid < 128) {
        int c = tid & 63, mi = tid >> 6;
        sF[mi * 64 + c] = fmaxf(sPM[c * 4 + 2 * mi], sPM[c * 4 + 2 * mi + 1]);
    }
    __syncthreads();

    // ---- output: out[n][o][m] = Wout[o,:64]@sF + Wout[o,64:67]@pre_xyz ----
    if (w < 6) {
        const int fo_mi = w / 3, fo_o = w - fo_mi * 3;
        const float* pxn = pre_xyz + n_ * 3 * M_;
        int m = m0 + fo_mi;
        float p = Wout[fo_o * 67 + lane] * sF[fo_mi * 64 + lane] +
                  Wout[fo_o * 67 + 32 + lane] * sF[fo_mi * 64 + 32 + lane];
#pragma unroll
        for (int off = 16; off >= 1; off >>= 1)
            p += __shfl_xor_sync(0xffffffffu, p, off);
        if (lane == 0) {
            p += Wout[fo_o * 67 + 64] * pxn[m] +
                 Wout[fo_o * 67 + 65] * pxn[M_ + m] +
                 Wout[fo_o * 67 + 66] * pxn[2 * M_ + m];
            out[n_ * 3 * M_ + fo_o * M_ + m] = p;
        }
    }
}

// ---------------- launcher ----------------
extern "C" void kernel_launch(void* const* d_in, const int* in_sizes, int n_in,
                              void* d_out, int out_size)
{
    const float* query     = (const float*)d_in[0];
    const float* scene_rgb = (const float*)d_in[1];
    const float* scene_xyz = (const float*)d_in[2];
    const float* pre_xyz   = (const float*)d_in[3];
    const float* mask      = (const float*)d_in[4];
    const float* W0        = (const float*)d_in[5];
    const float* g0        = (const float*)d_in[6];
    const float* b0        = (const float*)d_in[7];
    const float* m0        = (const float*)d_in[8];
    const float* v0        = (const float*)d_in[9];
    const float* W1a       = (const float*)d_in[10];
    const float* g1a       = (const float*)d_in[11];
    const float* b1a       = (const float*)d_in[12];
    const float* m1a       = (const float*)d_in[13];
    const float* v1a       = (const float*)d_in[14];
    const float* W1b       = (const float*)d_in[15];
    const float* g1b       = (const float*)d_in[16];
    const float* b1b       = (const float*)d_in[17];
    const float* m1b       = (const float*)d_in[18];
    const float* v1b       = (const float*)d_in[19];
    const float* Wskip     = (const float*)d_in[20];
    const float* Wout      = (const float*)d_in[21];
    float* out = (float*)d_out;

    prep_all<<<333, 256>>>(query, scene_rgb, scene_xyz, mask,
                           W0, W1a, W1b, Wskip,
                           g0, b0, m0, v0,
                           g1a, b1a, m1a, v1a,
                           g1b, b1b, m1b, v1b);

    cudaFuncSetAttribute(fused_main, cudaFuncAttributeMaxDynamicSharedMemorySize,
                         SMEM_FLOATS * 4);
    fused_main<<<N_ * (M_ / 2), 512, SMEM_FLOATS * 4>>>(pre_xyz, Wout, out);
}